// round 10
// baseline (speedup 1.0000x reference)
#include <cuda_runtime.h>
#include <cuda_bf16.h>
#include <math.h>
#include <stdint.h>

// Problem constants
#define S 128
#define B 32
#define E 300
#define H 200
#define G 800      // 4*H
#define NT 1600    // 2 dirs * G
#define MROWS 4096 // S*B
#define T 17

// Scratch (device globals). Wt*/X0/H0 hold tf32-converted bit patterns
// (stored as float bit-casts); GI*/H1 are true fp32.
__device__ float g_Wt0[300 * NT];
__device__ float g_Wt1[400 * NT];
__device__ float g_X0[MROWS * E];
__device__ float g_GI0[MROWS * NT];
__device__ float g_GI1[MROWS * NT];
__device__ float g_H0[MROWS * 400];
__device__ float g_H1[MROWS * 400];

__device__ __forceinline__ float sigf(float x) { return 1.0f / (1.0f + expf(-x)); }

__device__ __forceinline__ float ex2f(float x) {
    float y; asm("ex2.approx.f32 %0, %1;" : "=f"(y) : "f"(x)); return y;
}
__device__ __forceinline__ float rcpf(float x) {
    float y; asm("rcp.approx.f32 %0, %1;" : "=f"(y) : "f"(x)); return y;
}
__device__ __forceinline__ float fsig(float x) {   // 1/(1+e^-x)
    return rcpf(1.0f + ex2f(-1.4426950408889634f * x));
}
__device__ __forceinline__ float ftanh(float x) {  // 1 - 2/(1+e^{2x})
    return 1.0f - 2.0f * rcpf(1.0f + ex2f(2.8853901617779268f * x));
}

__device__ __forceinline__ uint32_t smem_u32(const void* p) {
    uint32_t a;
    asm("{ .reg .u64 t; cvta.to.shared.u64 t, %1; cvt.u32.u64 %0, t; }" : "=r"(a) : "l"(p));
    return a;
}
__device__ __forceinline__ void st_cluster_f32(uint32_t laddr, uint32_t rank, float v) {
    uint32_t ra;
    asm volatile("mapa.shared::cluster.u32 %0, %1, %2;" : "=r"(ra) : "r"(laddr), "r"(rank));
    asm volatile("st.shared::cluster.f32 [%0], %1;" :: "r"(ra), "f"(v) : "memory");
}
// Arrive (release, cluster scope) on the mbarrier at the same offset in CTA `rank`.
__device__ __forceinline__ void mbar_arrive_cluster(uint32_t mbar_addr, uint32_t rank) {
    asm volatile(
        "{ .reg .b32 ra;\n\t"
        "mapa.shared::cluster.u32 ra, %0, %1;\n\t"
        "mbarrier.arrive.release.cluster.shared::cluster.b64 _, [ra]; }"
        :: "r"(mbar_addr), "r"(rank) : "memory");
}
// Wait (acquire, cluster scope) on local mbarrier for phase `parity`.
__device__ __forceinline__ void mbar_wait_parity(uint32_t mbar_addr, uint32_t parity) {
    asm volatile(
        "{ .reg .pred P;\n\t"
        "WAIT_%=:\n\t"
        "mbarrier.try_wait.parity.acquire.cluster.shared::cta.b64 P, [%0], %1;\n\t"
        "@!P bra WAIT_%=; }"
        :: "r"(mbar_addr), "r"(parity) : "memory");
}
#define CL_ARRIVE() asm volatile("barrier.cluster.arrive.aligned;" ::: "memory")
#define CL_WAIT()   asm volatile("barrier.cluster.wait.aligned;" ::: "memory")

__device__ __forceinline__ uint32_t f2tf32(float f) {
    uint32_t u;
    asm("cvt.rna.tf32.f32 %0, %1;" : "=r"(u) : "f"(f));
    return u;
}
__device__ __forceinline__ uint64_t fma2(uint64_t a, uint64_t b, uint64_t c) {
    uint64_t d;
    asm("fma.rn.f32x2 %0, %1, %2, %3;" : "=l"(d) : "l"(a), "l"(b), "l"(c));
    return d;
}
__device__ __forceinline__ float2 unpack2(uint64_t v) {
    uint32_t lo, hi;
    asm("mov.b64 {%0,%1}, %2;" : "=r"(lo), "=r"(hi) : "l"(v));
    return make_float2(__uint_as_float(lo), __uint_as_float(hi));
}
__device__ __forceinline__ void mma_tf32(float* c, const uint32_t* a, const uint32_t* b) {
    asm volatile(
        "mma.sync.aligned.m16n8k8.row.col.f32.tf32.tf32.f32 "
        "{%0,%1,%2,%3}, {%4,%5,%6,%7}, {%8,%9}, {%0,%1,%2,%3};"
        : "+f"(c[0]), "+f"(c[1]), "+f"(c[2]), "+f"(c[3])
        : "r"(a[0]), "r"(a[1]), "r"(a[2]), "r"(a[3]), "r"(b[0]), "r"(b[1]));
}

// ---------------------------------------------------------------------------
// Fused prep
// ---------------------------------------------------------------------------
__global__ void prep(const float* __restrict__ Wih0, const float* __restrict__ Wih1,
                     const int* __restrict__ words, const float* __restrict__ emb) {
    const int task = blockIdx.y;
    const int idx = blockIdx.x * 256 + threadIdx.x;
    if (task == 0) {
        if (idx < NT * 300) {
            int n = idx / 300, k = idx - n * 300;
            g_Wt0[k * NT + n] = __uint_as_float(f2tf32(Wih0[idx]));
        }
    } else if (task == 1) {
        if (idx < NT * 400) {
            int n = idx / 400, k = idx - n * 400;
            g_Wt1[k * NT + n] = __uint_as_float(f2tf32(Wih1[idx]));
        }
    } else {
        if (idx < MROWS * 75) {
            int m = idx / 75, c4 = idx - m * 75;
            int s = m >> 5, b = m & 31;
            int w = words[b * S + s];
            float4 v = ((const float4*)(emb + (long long)w * E))[c4];
            float4 o;
            o.x = __uint_as_float(f2tf32(v.x));
            o.y = __uint_as_float(f2tf32(v.y));
            o.z = __uint_as_float(f2tf32(v.z));
            o.w = __uint_as_float(f2tf32(v.w));
            ((float4*)g_X0)[idx] = o;
        }
    }
}

// ---------------------------------------------------------------------------
// tf32 tensor-core GEMM (unchanged)
// ---------------------------------------------------------------------------
#define ASZ (128 * 20)
#define BSZ (16 * 72)
__global__ void __launch_bounds__(256) gemm_tc(const float* __restrict__ bias,
                                               int K, int layer) {
    const uint32_t* A  = (const uint32_t*)(layer ? g_H0  : g_X0);
    const uint32_t* Bm = (const uint32_t*)(layer ? g_Wt1 : g_Wt0);
    float* C           = layer ? g_GI1 : g_GI0;
    __shared__ uint32_t sm[2][ASZ + BSZ];

    const int tid = threadIdx.x;
    const int lane = tid & 31, wid = tid >> 5;
    const int g = lane >> 2, tg = lane & 3;
    const int warp_m = (wid & 3) * 32;
    const int warp_n = (wid >> 2) * 32;
    const int m0 = blockIdx.y * 128, n0 = blockIdx.x * 64;

    float acc[2][4][4] = {};
    const int ntiles = (K + 15) / 16;
    const int br = tid >> 4, bc4 = tid & 15;

    uint4 la[2], lb;
#pragma unroll
    for (int i = 0; i < 2; i++) {
        int idx = tid + i * 256;
        int r = idx >> 2, c4 = idx & 3;
        int kk = c4 * 4;
        uint4 v = make_uint4(0u, 0u, 0u, 0u);
        if (kk + 3 < K) v = *(const uint4*)&A[(m0 + r) * K + kk];
        else {
            if (kk + 0 < K) v.x = A[(m0 + r) * K + kk + 0];
            if (kk + 1 < K) v.y = A[(m0 + r) * K + kk + 1];
            if (kk + 2 < K) v.z = A[(m0 + r) * K + kk + 2];
            if (kk + 3 < K) v.w = A[(m0 + r) * K + kk + 3];
        }
        la[i] = v;
    }
    {
        lb = make_uint4(0u, 0u, 0u, 0u);
        if (br < K) lb = *(const uint4*)&Bm[br * NT + n0 + bc4 * 4];
    }
#pragma unroll
    for (int i = 0; i < 2; i++) {
        int idx = tid + i * 256;
        int r = idx >> 2, c4 = idx & 3;
        *(uint4*)&sm[0][r * 20 + c4 * 4] = la[i];
    }
    *(uint4*)&sm[0][ASZ + br * 72 + bc4 * 4] = lb;
    __syncthreads();

    int cur = 0;
    for (int t = 0; t < ntiles; t++) {
        if (t + 1 < ntiles) {
            const int k0 = (t + 1) * 16;
#pragma unroll
            for (int i = 0; i < 2; i++) {
                int idx = tid + i * 256;
                int r = idx >> 2, c4 = idx & 3;
                int kk = k0 + c4 * 4;
                uint4 v = make_uint4(0u, 0u, 0u, 0u);
                if (kk + 3 < K) v = *(const uint4*)&A[(m0 + r) * K + kk];
                else {
                    if (kk + 0 < K) v.x = A[(m0 + r) * K + kk + 0];
                    if (kk + 1 < K) v.y = A[(m0 + r) * K + kk + 1];
                    if (kk + 2 < K) v.z = A[(m0 + r) * K + kk + 2];
                    if (kk + 3 < K) v.w = A[(m0 + r) * K + kk + 3];
                }
                la[i] = v;
            }
            int kk = k0 + br;
            lb = make_uint4(0u, 0u, 0u, 0u);
            if (kk < K) lb = *(const uint4*)&Bm[kk * NT + n0 + bc4 * 4];
        }
        const uint32_t* As = sm[cur];
        const uint32_t* Bs = sm[cur] + ASZ;
#pragma unroll
        for (int k8 = 0; k8 < 16; k8 += 8) {
            uint32_t a[2][4], b[4][2];
#pragma unroll
            for (int mi = 0; mi < 2; mi++) {
                int row = warp_m + mi * 16;
                a[mi][0] = As[(row + g) * 20 + k8 + tg];
                a[mi][1] = As[(row + g + 8) * 20 + k8 + tg];
                a[mi][2] = As[(row + g) * 20 + k8 + tg + 4];
                a[mi][3] = As[(row + g + 8) * 20 + k8 + tg + 4];
            }
#pragma unroll
            for (int ni = 0; ni < 4; ni++) {
                int col = warp_n + ni * 8 + g;
                b[ni][0] = Bs[(k8 + tg) * 72 + col];
                b[ni][1] = Bs[(k8 + tg + 4) * 72 + col];
            }
#pragma unroll
            for (int mi = 0; mi < 2; mi++)
#pragma unroll
                for (int ni = 0; ni < 4; ni++)
                    mma_tf32(acc[mi][ni], a[mi], b[ni]);
        }
        if (t + 1 < ntiles) {
            uint32_t* d = sm[cur ^ 1];
#pragma unroll
            for (int i = 0; i < 2; i++) {
                int idx = tid + i * 256;
                int r = idx >> 2, c4 = idx & 3;
                *(uint4*)&d[r * 20 + c4 * 4] = la[i];
            }
            *(uint4*)&d[ASZ + br * 72 + bc4 * 4] = lb;
        }
        __syncthreads();
        cur ^= 1;
    }

#pragma unroll
    for (int mi = 0; mi < 2; mi++) {
        int r0 = m0 + warp_m + mi * 16 + g;
        int r1 = r0 + 8;
#pragma unroll
        for (int ni = 0; ni < 4; ni++) {
            int c = n0 + warp_n + ni * 8 + tg * 2;
            float2 bv = *(const float2*)&bias[c];
            float2 o0, o1;
            o0.x = acc[mi][ni][0] + bv.x; o0.y = acc[mi][ni][1] + bv.y;
            o1.x = acc[mi][ni][2] + bv.x; o1.y = acc[mi][ni][3] + bv.y;
            *(float2*)&C[(size_t)r0 * NT + c] = o0;
            *(float2*)&C[(size_t)r1 * NT + c] = o1;
        }
    }
}

// ---------------------------------------------------------------------------
// Cluster-resident LSTM recurrence, mbarrier-synchronized.
// 4-CTA cluster per (batch-pair, direction); CTA r owns j in [r*50, r*50+50).
// U slice (200x200 per CTA) entirely in registers as packed k-pairs.
// Per step: phase A (200 threads) computes gate pre-acts from local hbuf;
// __syncthreads; phase B (100 threads) updates cells, stores h to all 4 CTAs
// (st.shared::cluster) and arrives (release) on all 4 mbarriers; ALL threads
// then try_wait (acquire, parity=step&1) on the LOCAL mbarrier. The mbar wait
// replaces barrier.cluster (~490cyc) with TRYWAIT wakeup (~60-90cyc) and also
// serves as the block-wide phase fence (arrivals come from the ag readers).
// ---------------------------------------------------------------------------
__global__ void __cluster_dims__(4, 1, 1) __launch_bounds__(224, 1)
lstm_rec(const float* __restrict__ Whh, int layer) {
    const float* GI = layer ? g_GI1 : g_GI0;
    float* Hout     = layer ? g_H1  : g_H0;
    __shared__ __align__(16) float hbuf[2 * 2 * 200];  // [ping][batch01][j]
    __shared__ __align__(16) float ag[400];            // [gate][j][batch01]
    __shared__ __align__(8) uint64_t mbar;

    const int tid = threadIdx.x;     // 0..223
    uint32_t crank;
    asm("mov.u32 %0, %%cluster_ctarank;" : "=r"(crank));
    const int bg = blockIdx.y >> 1;
    const int d  = blockIdx.y & 1;
    const int bb0 = bg * 2;

    const int gate = (tid < 200) ? (tid / 50) : 0;
    const int jl   = (tid < 200) ? (tid % 50) : 0;
    const int jglob = crank * 50 + jl;

    const float* WhhD = Whh + (size_t)d * (G * H);

    // whole U row (200 floats) in registers as 100 packed k-pairs
    uint64_t upair[100];
    if (tid < 200) {
        const ulonglong2* Urow =
            (const ulonglong2*)(WhhD + (size_t)(gate * 200 + jglob) * 200);
#pragma unroll
        for (int kq = 0; kq < 50; kq++) {
            ulonglong2 t = Urow[kq];
            upair[2 * kq] = t.x;
            upair[2 * kq + 1] = t.y;
        }
    }
    for (int idx = tid; idx < 800; idx += 224) hbuf[idx] = 0.0f;
    const uint32_t hb_u32 = smem_u32(hbuf);
    const uint32_t mb_u32 = smem_u32(&mbar);
    if (tid == 0) {
        asm volatile("mbarrier.init.shared.b64 [%0], %1;"
                     :: "r"(mb_u32), "r"(400u) : "memory");
    }
    __syncthreads();
    CL_ARRIVE(); CL_WAIT();   // all CTAs: hbuf zeroed + mbar initialized

    float cst = 0.0f;
    int p = 0;

    for (int step = 0; step < 128; step++) {
        const int tstep = d ? (127 - step) : step;
        // ---- phase A: gate pre-activations ----
        if (tid < 200) {
            const float* gb = GI + (size_t)(tstep * B + bb0) * NT + d * 800
                              + gate * 200 + jglob;
            float gi0 = gb[0];
            float gi1 = gb[NT];
            const ulonglong2* hp0 = (const ulonglong2*)(hbuf + (p * 2 + 0) * 200);
            const ulonglong2* hp1 = (const ulonglong2*)(hbuf + (p * 2 + 1) * 200);
            uint64_t a00 = 0, a01 = 0, a10 = 0, a11 = 0;
#pragma unroll
            for (int kq = 0; kq < 50; kq++) {
                ulonglong2 h0 = hp0[kq];
                ulonglong2 h1 = hp1[kq];
                a00 = fma2(upair[2 * kq],     h0.x, a00);
                a01 = fma2(upair[2 * kq + 1], h0.y, a01);
                a10 = fma2(upair[2 * kq],     h1.x, a10);
                a11 = fma2(upair[2 * kq + 1], h1.y, a11);
            }
            float2 s00 = unpack2(a00), s01 = unpack2(a01);
            float2 s10 = unpack2(a10), s11 = unpack2(a11);
            ag[gate * 100 + jl * 2 + 0] = (s00.x + s00.y) + (s01.x + s01.y) + gi0;
            ag[gate * 100 + jl * 2 + 1] = (s10.x + s10.y) + (s11.x + s11.y) + gi1;
        }
        __syncthreads();
        // ---- phase B: cell update + cluster h broadcast + arrivals ----
        if (tid < 100) {
            float aI = ag[tid], aF = ag[100 + tid], aG = ag[200 + tid], aO = ag[300 + tid];
            cst = fsig(aF) * cst + fsig(aI) * ftanh(aG);
            float hv = fsig(aO) * ftanh(cst);
            const int b = tid & 1, jlc = tid >> 1;
            const int jg = (int)crank * 50 + jlc;
            const int pn = p ^ 1;
            const uint32_t ha = hb_u32 + (uint32_t)((((pn * 2 + b) * 200) + jg) * 4);
            st_cluster_f32(ha, 0, hv);
            st_cluster_f32(ha, 1, hv);
            st_cluster_f32(ha, 2, hv);
            st_cluster_f32(ha, 3, hv);
            float hstore = layer ? hv : __uint_as_float(f2tf32(hv));
            Hout[(size_t)(tstep * B + bb0 + b) * 400 + d * 200 + jg] = hstore;
            mbar_arrive_cluster(mb_u32, 0);
            mbar_arrive_cluster(mb_u32, 1);
            mbar_arrive_cluster(mb_u32, 2);
            mbar_arrive_cluster(mb_u32, 3);
        }
        // all threads wait for this step's 400 arrivals (h published cluster-wide)
        mbar_wait_parity(mb_u32, (uint32_t)(step & 1));
        p ^= 1;
    }
}

// ---------------------------------------------------------------------------
// Output projection
// ---------------------------------------------------------------------------
__global__ void out_proj(const float* __restrict__ ow,
                         const float* __restrict__ ob, float* __restrict__ out) {
    __shared__ float x[400];
    const int m = blockIdx.x; // s*B + b
    const int tid = threadIdx.x;
    for (int i = tid; i < 400; i += blockDim.x) x[i] = g_H1[m * 400 + i];
    __syncthreads();
    if (tid < 136) {
        const int tt = tid >> 3, l = tid & 7;
        float acc = 0.0f;
        for (int k = l; k < 400; k += 8) acc = fmaf(x[k], ow[tt * 400 + k], acc);
        unsigned mask = (tid < 128) ? 0xffffffffu : 0xffu;
        acc += __shfl_down_sync(mask, acc, 4, 8);
        acc += __shfl_down_sync(mask, acc, 2, 8);
        acc += __shfl_down_sync(mask, acc, 1, 8);
        if (l == 0) {
            int s = m >> 5, b = m & 31;
            out[(b * S + s) * T + tt] = sigf(acc + ob[tt]);
        }
    }
}

// ---------------------------------------------------------------------------
extern "C" void kernel_launch(void* const* d_in, const int* in_sizes, int n_in,
                              void* d_out, int out_size) {
    const int* words = (const int*)d_in[0];
    const float* emb = (const float*)d_in[3];
    const float* Wih0 = (const float*)d_in[7];
    const float* Whh0 = (const float*)d_in[8];
    const float* b0 = (const float*)d_in[9];
    const float* Wih1 = (const float*)d_in[10];
    const float* Whh1 = (const float*)d_in[11];
    const float* b1 = (const float*)d_in[12];
    const float* ow = (const float*)d_in[13];
    const float* ob = (const float*)d_in[14];
    float* out = (float*)d_out;

    prep<<<dim3(2500, 3), 256>>>(Wih0, Wih1, words, emb);
    gemm_tc<<<dim3(NT / 64, MROWS / 128), 256>>>(b0, 300, 0);
    lstm_rec<<<dim3(4, 32), 224>>>(Whh0, 0);
    gemm_tc<<<dim3(NT / 64, MROWS / 128), 256>>>(b1, 400, 1);
    lstm_rec<<<dim3(4, 32), 224>>>(Whh1, 1);
    out_proj<<<MROWS, 160>>>(ow, ob, out);
}

// round 11
// speedup vs baseline: 1.0986x; 1.0986x over previous
#include <cuda_runtime.h>
#include <cuda_bf16.h>
#include <math.h>
#include <stdint.h>

// Problem constants
#define S 128
#define B 32
#define E 300
#define H 200
#define G 800      // 4*H
#define NT 1600    // 2 dirs * G
#define MROWS 4096 // S*B
#define T 17

// Scratch (device globals). Wt*/X0/H0 hold tf32-converted bit patterns
// (stored as float bit-casts); GI*/H1 are true fp32.
__device__ float g_Wt0[300 * NT];
__device__ float g_Wt1[400 * NT];
__device__ float g_X0[MROWS * E];
__device__ float g_GI0[MROWS * NT];
__device__ float g_GI1[MROWS * NT];
__device__ float g_H0[MROWS * 400];
__device__ float g_H1[MROWS * 400];

__device__ __forceinline__ float sigf(float x) { return 1.0f / (1.0f + expf(-x)); }

__device__ __forceinline__ float ex2f(float x) {
    float y; asm("ex2.approx.f32 %0, %1;" : "=f"(y) : "f"(x)); return y;
}
__device__ __forceinline__ float rcpf(float x) {
    float y; asm("rcp.approx.f32 %0, %1;" : "=f"(y) : "f"(x)); return y;
}
__device__ __forceinline__ float fsig(float x) {   // 1/(1+e^-x)
    return rcpf(1.0f + ex2f(-1.4426950408889634f * x));
}
__device__ __forceinline__ float ftanh(float x) {  // 1 - 2/(1+e^{2x})
    return 1.0f - 2.0f * rcpf(1.0f + ex2f(2.8853901617779268f * x));
}

__device__ __forceinline__ uint32_t smem_u32(const void* p) {
    uint32_t a;
    asm("{ .reg .u64 t; cvta.to.shared.u64 t, %1; cvt.u32.u64 %0, t; }" : "=r"(a) : "l"(p));
    return a;
}
__device__ __forceinline__ void st_cluster_f32(uint32_t laddr, uint32_t rank, float v) {
    uint32_t ra;
    asm volatile("mapa.shared::cluster.u32 %0, %1, %2;" : "=r"(ra) : "r"(laddr), "r"(rank));
    asm volatile("st.shared::cluster.f32 [%0], %1;" :: "r"(ra), "f"(v) : "memory");
}
#define CL_ARRIVE() asm volatile("barrier.cluster.arrive.aligned;" ::: "memory")
#define CL_WAIT()   asm volatile("barrier.cluster.wait.aligned;" ::: "memory")
#define CLUSTER_SYNC_() do { CL_ARRIVE(); CL_WAIT(); } while (0)

__device__ __forceinline__ uint32_t f2tf32(float f) {
    uint32_t u;
    asm("cvt.rna.tf32.f32 %0, %1;" : "=r"(u) : "f"(f));
    return u;
}
__device__ __forceinline__ uint64_t fma2(uint64_t a, uint64_t b, uint64_t c) {
    uint64_t d;
    asm("fma.rn.f32x2 %0, %1, %2, %3;" : "=l"(d) : "l"(a), "l"(b), "l"(c));
    return d;
}
__device__ __forceinline__ float2 unpack2(uint64_t v) {
    uint32_t lo, hi;
    asm("mov.b64 {%0,%1}, %2;" : "=r"(lo), "=r"(hi) : "l"(v));
    return make_float2(__uint_as_float(lo), __uint_as_float(hi));
}
__device__ __forceinline__ void mma_tf32(float* c, const uint32_t* a, const uint32_t* b) {
    asm volatile(
        "mma.sync.aligned.m16n8k8.row.col.f32.tf32.tf32.f32 "
        "{%0,%1,%2,%3}, {%4,%5,%6,%7}, {%8,%9}, {%0,%1,%2,%3};"
        : "+f"(c[0]), "+f"(c[1]), "+f"(c[2]), "+f"(c[3])
        : "r"(a[0]), "r"(a[1]), "r"(a[2]), "r"(a[3]), "r"(b[0]), "r"(b[1]));
}

// ---------------------------------------------------------------------------
// Fused prep
// ---------------------------------------------------------------------------
__global__ void prep(const float* __restrict__ Wih0, const float* __restrict__ Wih1,
                     const int* __restrict__ words, const float* __restrict__ emb) {
    const int task = blockIdx.y;
    const int idx = blockIdx.x * 256 + threadIdx.x;
    if (task == 0) {
        if (idx < NT * 300) {
            int n = idx / 300, k = idx - n * 300;
            g_Wt0[k * NT + n] = __uint_as_float(f2tf32(Wih0[idx]));
        }
    } else if (task == 1) {
        if (idx < NT * 400) {
            int n = idx / 400, k = idx - n * 400;
            g_Wt1[k * NT + n] = __uint_as_float(f2tf32(Wih1[idx]));
        }
    } else {
        if (idx < MROWS * 75) {
            int m = idx / 75, c4 = idx - m * 75;
            int s = m >> 5, b = m & 31;
            int w = words[b * S + s];
            float4 v = ((const float4*)(emb + (long long)w * E))[c4];
            float4 o;
            o.x = __uint_as_float(f2tf32(v.x));
            o.y = __uint_as_float(f2tf32(v.y));
            o.z = __uint_as_float(f2tf32(v.z));
            o.w = __uint_as_float(f2tf32(v.w));
            ((float4*)g_X0)[idx] = o;
        }
    }
}

// ---------------------------------------------------------------------------
// tf32 tensor-core GEMM (unchanged from R8 best)
// ---------------------------------------------------------------------------
#define ASZ (128 * 20)
#define BSZ (16 * 72)
__global__ void __launch_bounds__(256) gemm_tc(const float* __restrict__ bias,
                                               int K, int layer) {
    const uint32_t* A  = (const uint32_t*)(layer ? g_H0  : g_X0);
    const uint32_t* Bm = (const uint32_t*)(layer ? g_Wt1 : g_Wt0);
    float* C           = layer ? g_GI1 : g_GI0;
    __shared__ uint32_t sm[2][ASZ + BSZ];

    const int tid = threadIdx.x;
    const int lane = tid & 31, wid = tid >> 5;
    const int g = lane >> 2, tg = lane & 3;
    const int warp_m = (wid & 3) * 32;
    const int warp_n = (wid >> 2) * 32;
    const int m0 = blockIdx.y * 128, n0 = blockIdx.x * 64;

    float acc[2][4][4] = {};
    const int ntiles = (K + 15) / 16;
    const int br = tid >> 4, bc4 = tid & 15;

    uint4 la[2], lb;
#pragma unroll
    for (int i = 0; i < 2; i++) {
        int idx = tid + i * 256;
        int r = idx >> 2, c4 = idx & 3;
        int kk = c4 * 4;
        uint4 v = make_uint4(0u, 0u, 0u, 0u);
        if (kk + 3 < K) v = *(const uint4*)&A[(m0 + r) * K + kk];
        else {
            if (kk + 0 < K) v.x = A[(m0 + r) * K + kk + 0];
            if (kk + 1 < K) v.y = A[(m0 + r) * K + kk + 1];
            if (kk + 2 < K) v.z = A[(m0 + r) * K + kk + 2];
            if (kk + 3 < K) v.w = A[(m0 + r) * K + kk + 3];
        }
        la[i] = v;
    }
    {
        lb = make_uint4(0u, 0u, 0u, 0u);
        if (br < K) lb = *(const uint4*)&Bm[br * NT + n0 + bc4 * 4];
    }
#pragma unroll
    for (int i = 0; i < 2; i++) {
        int idx = tid + i * 256;
        int r = idx >> 2, c4 = idx & 3;
        *(uint4*)&sm[0][r * 20 + c4 * 4] = la[i];
    }
    *(uint4*)&sm[0][ASZ + br * 72 + bc4 * 4] = lb;
    __syncthreads();

    int cur = 0;
    for (int t = 0; t < ntiles; t++) {
        if (t + 1 < ntiles) {
            const int k0 = (t + 1) * 16;
#pragma unroll
            for (int i = 0; i < 2; i++) {
                int idx = tid + i * 256;
                int r = idx >> 2, c4 = idx & 3;
                int kk = k0 + c4 * 4;
                uint4 v = make_uint4(0u, 0u, 0u, 0u);
                if (kk + 3 < K) v = *(const uint4*)&A[(m0 + r) * K + kk];
                else {
                    if (kk + 0 < K) v.x = A[(m0 + r) * K + kk + 0];
                    if (kk + 1 < K) v.y = A[(m0 + r) * K + kk + 1];
                    if (kk + 2 < K) v.z = A[(m0 + r) * K + kk + 2];
                    if (kk + 3 < K) v.w = A[(m0 + r) * K + kk + 3];
                }
                la[i] = v;
            }
            int kk = k0 + br;
            lb = make_uint4(0u, 0u, 0u, 0u);
            if (kk < K) lb = *(const uint4*)&Bm[kk * NT + n0 + bc4 * 4];
        }
        const uint32_t* As = sm[cur];
        const uint32_t* Bs = sm[cur] + ASZ;
#pragma unroll
        for (int k8 = 0; k8 < 16; k8 += 8) {
            uint32_t a[2][4], b[4][2];
#pragma unroll
            for (int mi = 0; mi < 2; mi++) {
                int row = warp_m + mi * 16;
                a[mi][0] = As[(row + g) * 20 + k8 + tg];
                a[mi][1] = As[(row + g + 8) * 20 + k8 + tg];
                a[mi][2] = As[(row + g) * 20 + k8 + tg + 4];
                a[mi][3] = As[(row + g + 8) * 20 + k8 + tg + 4];
            }
#pragma unroll
            for (int ni = 0; ni < 4; ni++) {
                int col = warp_n + ni * 8 + g;
                b[ni][0] = Bs[(k8 + tg) * 72 + col];
                b[ni][1] = Bs[(k8 + tg + 4) * 72 + col];
            }
#pragma unroll
            for (int mi = 0; mi < 2; mi++)
#pragma unroll
                for (int ni = 0; ni < 4; ni++)
                    mma_tf32(acc[mi][ni], a[mi], b[ni]);
        }
        if (t + 1 < ntiles) {
            uint32_t* d = sm[cur ^ 1];
#pragma unroll
            for (int i = 0; i < 2; i++) {
                int idx = tid + i * 256;
                int r = idx >> 2, c4 = idx & 3;
                *(uint4*)&d[r * 20 + c4 * 4] = la[i];
            }
            *(uint4*)&d[ASZ + br * 72 + bc4 * 4] = lb;
        }
        __syncthreads();
        cur ^= 1;
    }

#pragma unroll
    for (int mi = 0; mi < 2; mi++) {
        int r0 = m0 + warp_m + mi * 16 + g;
        int r1 = r0 + 8;
#pragma unroll
        for (int ni = 0; ni < 4; ni++) {
            int c = n0 + warp_n + ni * 8 + tg * 2;
            float2 bv = *(const float2*)&bias[c];
            float2 o0, o1;
            o0.x = acc[mi][ni][0] + bv.x; o0.y = acc[mi][ni][1] + bv.y;
            o1.x = acc[mi][ni][2] + bv.x; o1.y = acc[mi][ni][3] + bv.y;
            *(float2*)&C[(size_t)r0 * NT + c] = o0;
            *(float2*)&C[(size_t)r1 * NT + c] = o1;
        }
    }
}

// ---------------------------------------------------------------------------
// Cluster-resident LSTM recurrence — lane-grouped gates, barrier-free A->B.
// 4-CTA cluster per (batch-pair, direction); CTA r owns j in [r*50, r*50+50).
// Thread mapping: tid = j*4 + gate (j in [0,50), gate in [0,4)) — the four
// gates of a hidden unit occupy 4 ADJACENT LANES. Phase A accumulates as
// before (U in registers, h broadcast from SMEM, f32x2 FMA). Gate exchange
// is then 2 shfl.bfly rounds (xor1, xor2) + SELs INSIDE the warp — no
// __syncthreads, no SMEM staging. All 4 lanes of a group compute the cell
// update redundantly (identical, deterministic); h broadcast stores are
// split 2-per-lane across the group. One CLUSTER_SYNC per step total.
// ---------------------------------------------------------------------------
__global__ void __cluster_dims__(4, 1, 1) __launch_bounds__(224, 1)
lstm_rec(const float* __restrict__ Whh, int layer) {
    const float* GI = layer ? g_GI1 : g_GI0;
    float* Hout     = layer ? g_H1  : g_H0;
    __shared__ __align__(16) float hbuf[2 * 2 * 200];  // [ping][batch01][j]

    const int tid = threadIdx.x;     // 0..223 (200 active)
    uint32_t crank;
    asm("mov.u32 %0, %%cluster_ctarank;" : "=r"(crank));
    const int bg = blockIdx.y >> 1;
    const int d  = blockIdx.y & 1;
    const int bb0 = bg * 2;

    const bool active = tid < 200;
    const int j    = tid >> 2;          // 0..49
    const int g    = tid & 3;           // gate slot
    const int jglob = (int)crank * 50 + j;
    const unsigned shmask = (tid < 192) ? 0xffffffffu : 0x000000ffu;

    const float* WhhD = Whh + (size_t)d * (G * H);

    // whole U row (200 floats) for (gate g, jglob) in registers as k-pairs
    uint64_t upair[100];
    if (active) {
        const ulonglong2* Urow =
            (const ulonglong2*)(WhhD + (size_t)(g * 200 + jglob) * 200);
#pragma unroll
        for (int kq = 0; kq < 50; kq++) {
            ulonglong2 t = Urow[kq];
            upair[2 * kq] = t.x;
            upair[2 * kq + 1] = t.y;
        }
    }
    for (int idx = tid; idx < 800; idx += 224) hbuf[idx] = 0.0f;
    __syncthreads();
    CLUSTER_SYNC_();   // peers' hbuf zeroed before any remote h store

    const uint32_t hb_u32 = smem_u32(hbuf);
    float c0 = 0.0f, c1 = 0.0f;   // cell states (redundant across 4-lane group)
    int p = 0;

    // incremental GI pointer (gate g row for both batches)
    const int t0 = d ? 127 : 0;
    const long long gstep = d ? -(long long)(B * NT) : (long long)(B * NT);
    const float* gb = GI + (size_t)(t0 * B + bb0) * NT + d * 800 + g * 200 + jglob;
    float* ho = Hout + (size_t)(t0 * B + bb0) * 400 + d * 200 + jglob;
    const long long hstep = d ? -(long long)(B * 400) : (long long)(B * 400);

    for (int step = 0; step < 128; step++) {
        if (active) {
            float gi0 = gb[0];
            float gi1 = gb[NT];
            const ulonglong2* hp0 = (const ulonglong2*)(hbuf + (p * 2 + 0) * 200);
            const ulonglong2* hp1 = (const ulonglong2*)(hbuf + (p * 2 + 1) * 200);
            uint64_t a00 = 0, a01 = 0, a10 = 0, a11 = 0;
#pragma unroll
            for (int kq = 0; kq < 50; kq++) {
                ulonglong2 h0 = hp0[kq];
                ulonglong2 h1 = hp1[kq];
                a00 = fma2(upair[2 * kq],     h0.x, a00);
                a01 = fma2(upair[2 * kq + 1], h0.y, a01);
                a10 = fma2(upair[2 * kq],     h1.x, a10);
                a11 = fma2(upair[2 * kq + 1], h1.y, a11);
            }
            float2 s00 = unpack2(a00), s01 = unpack2(a01);
            float2 s10 = unpack2(a10), s11 = unpack2(a11);
            float x0 = (s00.x + s00.y) + (s01.x + s01.y) + gi0;  // gate g, batch0
            float x1 = (s10.x + s10.y) + (s11.x + s11.y) + gi1;  // gate g, batch1

            // intra-group gate exchange: bfly xor1 then xor2 (+SEL ordering)
            const bool go = (g & 1), gh = (g & 2);
            float xp0 = __shfl_xor_sync(shmask, x0, 1);
            float xp1 = __shfl_xor_sync(shmask, x1, 1);
            float e0 = go ? xp0 : x0,  o0 = go ? x0 : xp0;   // even/odd gate of own pair
            float e1 = go ? xp1 : x1,  o1 = go ? x1 : xp1;
            float ep0 = __shfl_xor_sync(shmask, e0, 2);
            float op0 = __shfl_xor_sync(shmask, o0, 2);
            float ep1 = __shfl_xor_sync(shmask, e1, 2);
            float op1 = __shfl_xor_sync(shmask, o1, 2);
            float aI0 = gh ? ep0 : e0, aF0 = gh ? op0 : o0;
            float aG0 = gh ? e0 : ep0, aO0 = gh ? o0 : op0;
            float aI1 = gh ? ep1 : e1, aF1 = gh ? op1 : o1;
            float aG1 = gh ? e1 : ep1, aO1 = gh ? o1 : op1;

            // cell update (all 4 lanes, identical per group)
            c0 = fsig(aF0) * c0 + fsig(aI0) * ftanh(aG0);
            float hv0 = fsig(aO0) * ftanh(c0);
            c1 = fsig(aF1) * c1 + fsig(aI1) * ftanh(aG1);
            float hv1 = fsig(aO1) * ftanh(c1);

            // distribute the 8 (batch, rank) stores across the 4 lanes
            const int b = g & 1;
            const float hvb = b ? hv1 : hv0;
            const int pn = p ^ 1;
            const uint32_t ha = hb_u32 + (uint32_t)((((pn * 2 + b) * 200) + jglob) * 4);
            const uint32_t r0 = (uint32_t)(g >> 1);
            st_cluster_f32(ha, r0, hvb);
            st_cluster_f32(ha, r0 + 2, hvb);
            if (g < 2) {  // g=0 -> batch0, g=1 -> batch1 global store
                ho[(size_t)b * 400] = layer ? hvb : __uint_as_float(f2tf32(hvb));
            }
            gb += gstep;
            ho += hstep;
        }
        CLUSTER_SYNC_();  // h published cluster-wide; also fences local hbuf
        p ^= 1;
    }
}

// ---------------------------------------------------------------------------
// Output projection
// ---------------------------------------------------------------------------
__global__ void out_proj(const float* __restrict__ ow,
                         const float* __restrict__ ob, float* __restrict__ out) {
    __shared__ float x[400];
    const int m = blockIdx.x; // s*B + b
    const int tid = threadIdx.x;
    for (int i = tid; i < 400; i += blockDim.x) x[i] = g_H1[m * 400 + i];
    __syncthreads();
    if (tid < 136) {
        const int tt = tid >> 3, l = tid & 7;
        float acc = 0.0f;
        for (int k = l; k < 400; k += 8) acc = fmaf(x[k], ow[tt * 400 + k], acc);
        unsigned mask = (tid < 128) ? 0xffffffffu : 0xffu;
        acc += __shfl_down_sync(mask, acc, 4, 8);
        acc += __shfl_down_sync(mask, acc, 2, 8);
        acc += __shfl_down_sync(mask, acc, 1, 8);
        if (l == 0) {
            int s = m >> 5, b = m & 31;
            out[(b * S + s) * T + tt] = sigf(acc + ob[tt]);
        }
    }
}

// ---------------------------------------------------------------------------
extern "C" void kernel_launch(void* const* d_in, const int* in_sizes, int n_in,
                              void* d_out, int out_size) {
    const int* words = (const int*)d_in[0];
    const float* emb = (const float*)d_in[3];
    const float* Wih0 = (const float*)d_in[7];
    const float* Whh0 = (const float*)d_in[8];
    const float* b0 = (const float*)d_in[9];
    const float* Wih1 = (const float*)d_in[10];
    const float* Whh1 = (const float*)d_in[11];
    const float* b1 = (const float*)d_in[12];
    const float* ow = (const float*)d_in[13];
    const float* ob = (const float*)d_in[14];
    float* out = (float*)d_out;

    prep<<<dim3(2500, 3), 256>>>(Wih0, Wih1, words, emb);
    gemm_tc<<<dim3(NT / 64, MROWS / 128), 256>>>(b0, 300, 0);
    lstm_rec<<<dim3(4, 32), 224>>>(Whh0, 0);
    gemm_tc<<<dim3(NT / 64, MROWS / 128), 256>>>(b1, 400, 1);
    lstm_rec<<<dim3(4, 32), 224>>>(Whh1, 1);
    out_proj<<<MROWS, 160>>>(ow, ob, out);
}

// round 13
// speedup vs baseline: 1.1289x; 1.0276x over previous
#include <cuda_runtime.h>
#include <cuda_bf16.h>
#include <math.h>
#include <stdint.h>

// Problem constants
#define S 128
#define B 32
#define E 300
#define H 200
#define G 800      // 4*H
#define NT 1600    // 2 dirs * G
#define MROWS 4096 // S*B
#define T 17

// Scratch (device globals). Wt*/X0/H0 hold tf32-converted bit patterns
// (stored as float bit-casts); GI*/H1 are true fp32.
__device__ float g_Wt0[300 * NT];
__device__ float g_Wt1[400 * NT];
__device__ float g_X0[MROWS * E];
__device__ float g_GI0[MROWS * NT];
__device__ float g_GI1[MROWS * NT];
__device__ float g_H0[MROWS * 400];
__device__ float g_H1[MROWS * 400];

__device__ __forceinline__ float sigf(float x) { return 1.0f / (1.0f + expf(-x)); }

__device__ __forceinline__ float ex2f(float x) {
    float y; asm("ex2.approx.f32 %0, %1;" : "=f"(y) : "f"(x)); return y;
}
__device__ __forceinline__ float rcpf(float x) {
    float y; asm("rcp.approx.f32 %0, %1;" : "=f"(y) : "f"(x)); return y;
}
__device__ __forceinline__ float fsig(float x) {   // 1/(1+e^-x)
    return rcpf(1.0f + ex2f(-1.4426950408889634f * x));
}
__device__ __forceinline__ float ftanh(float x) {  // 1 - 2/(1+e^{2x})
    return 1.0f - 2.0f * rcpf(1.0f + ex2f(2.8853901617779268f * x));
}

__device__ __forceinline__ uint32_t smem_u32(const void* p) {
    uint32_t a;
    asm("{ .reg .u64 t; cvta.to.shared.u64 t, %1; cvt.u32.u64 %0, t; }" : "=r"(a) : "l"(p));
    return a;
}
__device__ __forceinline__ void st_cluster_f32(uint32_t laddr, uint32_t rank, float v) {
    uint32_t ra;
    asm volatile("mapa.shared::cluster.u32 %0, %1, %2;" : "=r"(ra) : "r"(laddr), "r"(rank));
    asm volatile("st.shared::cluster.f32 [%0], %1;" :: "r"(ra), "f"(v) : "memory");
}
#define CL_ARRIVE() asm volatile("barrier.cluster.arrive.aligned;" ::: "memory")
#define CL_WAIT()   asm volatile("barrier.cluster.wait.aligned;" ::: "memory")
#define CLUSTER_SYNC_() do { CL_ARRIVE(); CL_WAIT(); } while (0)

__device__ __forceinline__ uint32_t f2tf32(float f) {
    uint32_t u;
    asm("cvt.rna.tf32.f32 %0, %1;" : "=r"(u) : "f"(f));
    return u;
}
__device__ __forceinline__ uint64_t fma2(uint64_t a, uint64_t b, uint64_t c) {
    uint64_t d;
    asm("fma.rn.f32x2 %0, %1, %2, %3;" : "=l"(d) : "l"(a), "l"(b), "l"(c));
    return d;
}
__device__ __forceinline__ float2 unpack2(uint64_t v) {
    uint32_t lo, hi;
    asm("mov.b64 {%0,%1}, %2;" : "=r"(lo), "=r"(hi) : "l"(v));
    return make_float2(__uint_as_float(lo), __uint_as_float(hi));
}
__device__ __forceinline__ void mma_tf32(float* c, const uint32_t* a, const uint32_t* b) {
    asm volatile(
        "mma.sync.aligned.m16n8k8.row.col.f32.tf32.tf32.f32 "
        "{%0,%1,%2,%3}, {%4,%5,%6,%7}, {%8,%9}, {%0,%1,%2,%3};"
        : "+f"(c[0]), "+f"(c[1]), "+f"(c[2]), "+f"(c[3])
        : "r"(a[0]), "r"(a[1]), "r"(a[2]), "r"(a[3]), "r"(b[0]), "r"(b[1]));
}

// ---------------------------------------------------------------------------
// Fused prep
// ---------------------------------------------------------------------------
__global__ void prep(const float* __restrict__ Wih0, const float* __restrict__ Wih1,
                     const int* __restrict__ words, const float* __restrict__ emb) {
    const int task = blockIdx.y;
    const int idx = blockIdx.x * 256 + threadIdx.x;
    if (task == 0) {
        if (idx < NT * 300) {
            int n = idx / 300, k = idx - n * 300;
            g_Wt0[k * NT + n] = __uint_as_float(f2tf32(Wih0[idx]));
        }
    } else if (task == 1) {
        if (idx < NT * 400) {
            int n = idx / 400, k = idx - n * 400;
            g_Wt1[k * NT + n] = __uint_as_float(f2tf32(Wih1[idx]));
        }
    } else {
        if (idx < MROWS * 75) {
            int m = idx / 75, c4 = idx - m * 75;
            int s = m >> 5, b = m & 31;
            int w = words[b * S + s];
            float4 v = ((const float4*)(emb + (long long)w * E))[c4];
            float4 o;
            o.x = __uint_as_float(f2tf32(v.x));
            o.y = __uint_as_float(f2tf32(v.y));
            o.z = __uint_as_float(f2tf32(v.z));
            o.w = __uint_as_float(f2tf32(v.w));
            ((float4*)g_X0)[idx] = o;
        }
    }
}

// ---------------------------------------------------------------------------
// tf32 tensor-core GEMM: C = A*Bm + bias
// BM=256, BN=64, BK=16, 256 threads (8 warps: 4m x 2n), warp tile 64x32,
// mma.m16n8k8.tf32, double-buffered DYNAMIC SMEM (50176 B > 48KB static cap).
// As: [256][20] pad; Bs: [16][72] pad. Per k8: 24 LDS / 16 mma per warp.
// ---------------------------------------------------------------------------
#define ASZ (256 * 20)
#define BSZ (16 * 72)
#define GEMM_SMEM (2 * (ASZ + BSZ) * 4)
__global__ void __launch_bounds__(256) gemm_tc(const float* __restrict__ bias,
                                               int K, int layer) {
    const uint32_t* A  = (const uint32_t*)(layer ? g_H0  : g_X0);
    const uint32_t* Bm = (const uint32_t*)(layer ? g_Wt1 : g_Wt0);
    float* C           = layer ? g_GI1 : g_GI0;
    extern __shared__ uint32_t smd[];
    uint32_t* smbuf[2] = { smd, smd + (ASZ + BSZ) };

    const int tid = threadIdx.x;
    const int lane = tid & 31, wid = tid >> 5;
    const int g = lane >> 2, tg = lane & 3;
    const int warp_m = (wid & 3) * 64;    // 0,64,128,192
    const int warp_n = (wid >> 2) * 32;   // 0,32
    const int m0 = blockIdx.y * 256, n0 = blockIdx.x * 64;

    float acc[4][4][4] = {};
    const int ntiles = (K + 15) / 16;
    const int br = tid >> 4, bc4 = tid & 15;

    uint4 la[4], lb;
    // prefetch tile 0
#pragma unroll
    for (int i = 0; i < 4; i++) {
        int idx = tid + i * 256;
        int r = idx >> 2, c4 = idx & 3;
        int kk = c4 * 4;
        uint4 v = make_uint4(0u, 0u, 0u, 0u);
        if (kk + 3 < K) v = *(const uint4*)&A[(size_t)(m0 + r) * K + kk];
        else {
            if (kk + 0 < K) v.x = A[(size_t)(m0 + r) * K + kk + 0];
            if (kk + 1 < K) v.y = A[(size_t)(m0 + r) * K + kk + 1];
            if (kk + 2 < K) v.z = A[(size_t)(m0 + r) * K + kk + 2];
            if (kk + 3 < K) v.w = A[(size_t)(m0 + r) * K + kk + 3];
        }
        la[i] = v;
    }
    {
        lb = make_uint4(0u, 0u, 0u, 0u);
        if (br < K) lb = *(const uint4*)&Bm[(size_t)br * NT + n0 + bc4 * 4];
    }
#pragma unroll
    for (int i = 0; i < 4; i++) {
        int idx = tid + i * 256;
        int r = idx >> 2, c4 = idx & 3;
        *(uint4*)&smbuf[0][r * 20 + c4 * 4] = la[i];
    }
    *(uint4*)&smbuf[0][ASZ + br * 72 + bc4 * 4] = lb;
    __syncthreads();

    int cur = 0;
    for (int t = 0; t < ntiles; t++) {
        if (t + 1 < ntiles) {
            const int k0 = (t + 1) * 16;
#pragma unroll
            for (int i = 0; i < 4; i++) {
                int idx = tid + i * 256;
                int r = idx >> 2, c4 = idx & 3;
                int kk = k0 + c4 * 4;
                uint4 v = make_uint4(0u, 0u, 0u, 0u);
                if (kk + 3 < K) v = *(const uint4*)&A[(size_t)(m0 + r) * K + kk];
                else {
                    if (kk + 0 < K) v.x = A[(size_t)(m0 + r) * K + kk + 0];
                    if (kk + 1 < K) v.y = A[(size_t)(m0 + r) * K + kk + 1];
                    if (kk + 2 < K) v.z = A[(size_t)(m0 + r) * K + kk + 2];
                    if (kk + 3 < K) v.w = A[(size_t)(m0 + r) * K + kk + 3];
                }
                la[i] = v;
            }
            int kk = k0 + br;
            lb = make_uint4(0u, 0u, 0u, 0u);
            if (kk < K) lb = *(const uint4*)&Bm[(size_t)kk * NT + n0 + bc4 * 4];
        }
        const uint32_t* As = smbuf[cur];
        const uint32_t* Bs = smbuf[cur] + ASZ;
#pragma unroll
        for (int k8 = 0; k8 < 16; k8 += 8) {
            uint32_t a[4][4], b[4][2];
#pragma unroll
            for (int mi = 0; mi < 4; mi++) {
                int row = warp_m + mi * 16;
                a[mi][0] = As[(row + g) * 20 + k8 + tg];
                a[mi][1] = As[(row + g + 8) * 20 + k8 + tg];
                a[mi][2] = As[(row + g) * 20 + k8 + tg + 4];
                a[mi][3] = As[(row + g + 8) * 20 + k8 + tg + 4];
            }
#pragma unroll
            for (int ni = 0; ni < 4; ni++) {
                int col = warp_n + ni * 8 + g;
                b[ni][0] = Bs[(k8 + tg) * 72 + col];
                b[ni][1] = Bs[(k8 + tg + 4) * 72 + col];
            }
#pragma unroll
            for (int mi = 0; mi < 4; mi++)
#pragma unroll
                for (int ni = 0; ni < 4; ni++)
                    mma_tf32(acc[mi][ni], a[mi], b[ni]);
        }
        if (t + 1 < ntiles) {
            uint32_t* dd = smbuf[cur ^ 1];
#pragma unroll
            for (int i = 0; i < 4; i++) {
                int idx = tid + i * 256;
                int r = idx >> 2, c4 = idx & 3;
                *(uint4*)&dd[r * 20 + c4 * 4] = la[i];
            }
            *(uint4*)&dd[ASZ + br * 72 + bc4 * 4] = lb;
        }
        __syncthreads();
        cur ^= 1;
    }

#pragma unroll
    for (int mi = 0; mi < 4; mi++) {
        int r0 = m0 + warp_m + mi * 16 + g;
        int r1 = r0 + 8;
#pragma unroll
        for (int ni = 0; ni < 4; ni++) {
            int c = n0 + warp_n + ni * 8 + tg * 2;
            float2 bv = *(const float2*)&bias[c];
            float2 o0, o1;
            o0.x = acc[mi][ni][0] + bv.x; o0.y = acc[mi][ni][1] + bv.y;
            o1.x = acc[mi][ni][2] + bv.x; o1.y = acc[mi][ni][3] + bv.y;
            *(float2*)&C[(size_t)r0 * NT + c] = o0;
            *(float2*)&C[(size_t)r1 * NT + c] = o1;
        }
    }
}

// ---------------------------------------------------------------------------
// Cluster-resident LSTM recurrence — R8 structure (best measured), fast gates.
// 4-CTA cluster per (batch-pair, direction); CTA r owns j in [r*50, r*50+50).
// U slice entirely in registers as packed k-pairs; h broadcast from SMEM;
// phase A (200 thr) -> __syncthreads -> phase B (100 thr) -> CLUSTER_SYNC.
// ---------------------------------------------------------------------------
__global__ void __cluster_dims__(4, 1, 1) __launch_bounds__(224, 1)
lstm_rec(const float* __restrict__ Whh, int layer) {
    const float* GI = layer ? g_GI1 : g_GI0;
    float* Hout     = layer ? g_H1  : g_H0;
    __shared__ __align__(16) float hbuf[2 * 2 * 200];  // [ping][batch01][j]
    __shared__ __align__(16) float ag[400];            // [gate][j][batch01]

    const int tid = threadIdx.x;     // 0..223
    uint32_t crank;
    asm("mov.u32 %0, %%cluster_ctarank;" : "=r"(crank));
    const int bg = blockIdx.y >> 1;
    const int d  = blockIdx.y & 1;
    const int bb0 = bg * 2;

    const int gate = (tid < 200) ? (tid / 50) : 0;
    const int jl   = (tid < 200) ? (tid % 50) : 0;
    const int jglob = (int)crank * 50 + jl;

    const float* WhhD = Whh + (size_t)d * (G * H);

    // whole U row (200 floats) in registers as 100 packed k-pairs
    uint64_t upair[100];
    if (tid < 200) {
        const ulonglong2* Urow =
            (const ulonglong2*)(WhhD + (size_t)(gate * 200 + jglob) * 200);
#pragma unroll
        for (int kq = 0; kq < 50; kq++) {
            ulonglong2 t = Urow[kq];
            upair[2 * kq] = t.x;
            upair[2 * kq + 1] = t.y;
        }
    }
    for (int idx = tid; idx < 800; idx += 224) hbuf[idx] = 0.0f;
    __syncthreads();
    CLUSTER_SYNC_();   // peers' hbuf zeroed before any remote h store

    const uint32_t hb_u32 = smem_u32(hbuf);
    float cst = 0.0f;
    int p = 0;

    for (int step = 0; step < 128; step++) {
        const int tstep = d ? (127 - step) : step;
        // ---- phase A: gate pre-activations ----
        if (tid < 200) {
            const float* gb = GI + (size_t)(tstep * B + bb0) * NT + d * 800
                              + gate * 200 + jglob;
            float gi0 = gb[0];
            float gi1 = gb[NT];
            const ulonglong2* hp0 = (const ulonglong2*)(hbuf + (p * 2 + 0) * 200);
            const ulonglong2* hp1 = (const ulonglong2*)(hbuf + (p * 2 + 1) * 200);
            uint64_t a00 = 0, a01 = 0, a10 = 0, a11 = 0;
#pragma unroll
            for (int kq = 0; kq < 50; kq++) {
                ulonglong2 h0 = hp0[kq];
                ulonglong2 h1 = hp1[kq];
                a00 = fma2(upair[2 * kq],     h0.x, a00);
                a01 = fma2(upair[2 * kq + 1], h0.y, a01);
                a10 = fma2(upair[2 * kq],     h1.x, a10);
                a11 = fma2(upair[2 * kq + 1], h1.y, a11);
            }
            float2 s00 = unpack2(a00), s01 = unpack2(a01);
            float2 s10 = unpack2(a10), s11 = unpack2(a11);
            ag[gate * 100 + jl * 2 + 0] = (s00.x + s00.y) + (s01.x + s01.y) + gi0;
            ag[gate * 100 + jl * 2 + 1] = (s10.x + s10.y) + (s11.x + s11.y) + gi1;
        }
        __syncthreads();
        // ---- phase B: cell update + cluster h broadcast (fast gates) ----
        if (tid < 100) {
            float aI = ag[tid], aF = ag[100 + tid], aG = ag[200 + tid], aO = ag[300 + tid];
            cst = fsig(aF) * cst + fsig(aI) * ftanh(aG);
            float hv = fsig(aO) * ftanh(cst);
            const int b = tid & 1, jlc = tid >> 1;
            const int jg = (int)crank * 50 + jlc;
            const int pn = p ^ 1;
            const uint32_t ha = hb_u32 + (uint32_t)((((pn * 2 + b) * 200) + jg) * 4);
            st_cluster_f32(ha, 0, hv);
            st_cluster_f32(ha, 1, hv);
            st_cluster_f32(ha, 2, hv);
            st_cluster_f32(ha, 3, hv);
            float hstore = layer ? hv : __uint_as_float(f2tf32(hv));
            Hout[(size_t)(tstep * B + bb0 + b) * 400 + d * 200 + jg] = hstore;
        }
        CLUSTER_SYNC_();  // h published cluster-wide; also fences ag reuse
        p ^= 1;
    }
}

// ---------------------------------------------------------------------------
// Output projection
// ---------------------------------------------------------------------------
__global__ void out_proj(const float* __restrict__ ow,
                         const float* __restrict__ ob, float* __restrict__ out) {
    __shared__ float x[400];
    const int m = blockIdx.x; // s*B + b
    const int tid = threadIdx.x;
    for (int i = tid; i < 400; i += blockDim.x) x[i] = g_H1[m * 400 + i];
    __syncthreads();
    if (tid < 136) {
        const int tt = tid >> 3, l = tid & 7;
        float acc = 0.0f;
        for (int k = l; k < 400; k += 8) acc = fmaf(x[k], ow[tt * 400 + k], acc);
        unsigned mask = (tid < 128) ? 0xffffffffu : 0xffu;
        acc += __shfl_down_sync(mask, acc, 4, 8);
        acc += __shfl_down_sync(mask, acc, 2, 8);
        acc += __shfl_down_sync(mask, acc, 1, 8);
        if (l == 0) {
            int s = m >> 5, b = m & 31;
            out[(b * S + s) * T + tt] = sigf(acc + ob[tt]);
        }
    }
}

// ---------------------------------------------------------------------------
extern "C" void kernel_launch(void* const* d_in, const int* in_sizes, int n_in,
                              void* d_out, int out_size) {
    const int* words = (const int*)d_in[0];
    const float* emb = (const float*)d_in[3];
    const float* Wih0 = (const float*)d_in[7];
    const float* Whh0 = (const float*)d_in[8];
    const float* b0 = (const float*)d_in[9];
    const float* Wih1 = (const float*)d_in[10];
    const float* Whh1 = (const float*)d_in[11];
    const float* b1 = (const float*)d_in[12];
    const float* ow = (const float*)d_in[13];
    const float* ob = (const float*)d_in[14];
    float* out = (float*)d_out;

    // unconditional, capture-safe host call (proven in R7's passing run)
    cudaFuncSetAttribute(gemm_tc, cudaFuncAttributeMaxDynamicSharedMemorySize,
                         GEMM_SMEM);

    prep<<<dim3(2500, 3), 256>>>(Wih0, Wih1, words, emb);
    gemm_tc<<<dim3(NT / 64, MROWS / 256), 256, GEMM_SMEM>>>(b0, 300, 0);
    lstm_rec<<<dim3(4, 32), 224>>>(Whh0, 0);
    gemm_tc<<<dim3(NT / 64, MROWS / 256), 256, GEMM_SMEM>>>(b1, 400, 1);
    lstm_rec<<<dim3(4, 32), 224>>>(Whh1, 1);
    out_proj<<<MROWS, 160>>>(ow, ob, out);
}

// round 14
// speedup vs baseline: 1.1473x; 1.0163x over previous
#include <cuda_runtime.h>
#include <cuda_bf16.h>
#include <math.h>
#include <stdint.h>

// Problem constants
#define S 128
#define B 32
#define E 300
#define H 200
#define G 800      // 4*H
#define NT 1600    // 2 dirs * G
#define MROWS 4096 // S*B
#define T 17

// Scratch (device globals). Wt*/X0/H0 hold tf32-converted bit patterns
// (stored as float bit-casts); GI*/H1 are true fp32.
__device__ float g_Wt0[300 * NT];
__device__ float g_Wt1[400 * NT];
__device__ float g_X0[MROWS * E];
__device__ float g_GI0[MROWS * NT];
__device__ float g_GI1[MROWS * NT];
__device__ float g_H0[MROWS * 400];
__device__ float g_H1[MROWS * 400];

__device__ __forceinline__ float sigf(float x) { return 1.0f / (1.0f + expf(-x)); }

__device__ __forceinline__ float ex2f(float x) {
    float y; asm("ex2.approx.f32 %0, %1;" : "=f"(y) : "f"(x)); return y;
}
__device__ __forceinline__ float rcpf(float x) {
    float y; asm("rcp.approx.f32 %0, %1;" : "=f"(y) : "f"(x)); return y;
}
__device__ __forceinline__ float fsig(float x) {   // 1/(1+e^-x)
    return rcpf(1.0f + ex2f(-1.4426950408889634f * x));
}
__device__ __forceinline__ float ftanh(float x) {  // 1 - 2/(1+e^{2x})
    return 1.0f - 2.0f * rcpf(1.0f + ex2f(2.8853901617779268f * x));
}

__device__ __forceinline__ uint32_t smem_u32(const void* p) {
    uint32_t a;
    asm("{ .reg .u64 t; cvta.to.shared.u64 t, %1; cvt.u32.u64 %0, t; }" : "=r"(a) : "l"(p));
    return a;
}
__device__ __forceinline__ void st_cluster_f32(uint32_t laddr, uint32_t rank, float v) {
    uint32_t ra;
    asm volatile("mapa.shared::cluster.u32 %0, %1, %2;" : "=r"(ra) : "r"(laddr), "r"(rank));
    asm volatile("st.shared::cluster.f32 [%0], %1;" :: "r"(ra), "f"(v) : "memory");
}
#define CL_ARRIVE() asm volatile("barrier.cluster.arrive.aligned;" ::: "memory")
#define CL_WAIT()   asm volatile("barrier.cluster.wait.aligned;" ::: "memory")
#define CLUSTER_SYNC_() do { CL_ARRIVE(); CL_WAIT(); } while (0)

__device__ __forceinline__ uint32_t f2tf32(float f) {
    uint32_t u;
    asm("cvt.rna.tf32.f32 %0, %1;" : "=r"(u) : "f"(f));
    return u;
}
__device__ __forceinline__ uint64_t fma2(uint64_t a, uint64_t b, uint64_t c) {
    uint64_t d;
    asm("fma.rn.f32x2 %0, %1, %2, %3;" : "=l"(d) : "l"(a), "l"(b), "l"(c));
    return d;
}
__device__ __forceinline__ float2 unpack2(uint64_t v) {
    uint32_t lo, hi;
    asm("mov.b64 {%0,%1}, %2;" : "=r"(lo), "=r"(hi) : "l"(v));
    return make_float2(__uint_as_float(lo), __uint_as_float(hi));
}
__device__ __forceinline__ void mma_tf32(float* c, const uint32_t* a, const uint32_t* b) {
    asm volatile(
        "mma.sync.aligned.m16n8k8.row.col.f32.tf32.tf32.f32 "
        "{%0,%1,%2,%3}, {%4,%5,%6,%7}, {%8,%9}, {%0,%1,%2,%3};"
        : "+f"(c[0]), "+f"(c[1]), "+f"(c[2]), "+f"(c[3])
        : "r"(a[0]), "r"(a[1]), "r"(a[2]), "r"(a[3]), "r"(b[0]), "r"(b[1]));
}

// ---------------------------------------------------------------------------
// Fused prep
// ---------------------------------------------------------------------------
__global__ void prep(const float* __restrict__ Wih0, const float* __restrict__ Wih1,
                     const int* __restrict__ words, const float* __restrict__ emb) {
    const int task = blockIdx.y;
    const int idx = blockIdx.x * 256 + threadIdx.x;
    if (task == 0) {
        if (idx < NT * 300) {
            int n = idx / 300, k = idx - n * 300;
            g_Wt0[k * NT + n] = __uint_as_float(f2tf32(Wih0[idx]));
        }
    } else if (task == 1) {
        if (idx < NT * 400) {
            int n = idx / 400, k = idx - n * 400;
            g_Wt1[k * NT + n] = __uint_as_float(f2tf32(Wih1[idx]));
        }
    } else {
        if (idx < MROWS * 75) {
            int m = idx / 75, c4 = idx - m * 75;
            int s = m >> 5, b = m & 31;
            int w = words[b * S + s];
            float4 v = ((const float4*)(emb + (long long)w * E))[c4];
            float4 o;
            o.x = __uint_as_float(f2tf32(v.x));
            o.y = __uint_as_float(f2tf32(v.y));
            o.z = __uint_as_float(f2tf32(v.z));
            o.w = __uint_as_float(f2tf32(v.w));
            ((float4*)g_X0)[idx] = o;
        }
    }
}

// ---------------------------------------------------------------------------
// tf32 tensor-core GEMM — R8 verbatim (best measured: 66.6us).
// BM=128, BN=64, BK=16, 256 threads (8 warps, 4x2), warp tile 32x32,
// mma.m16n8k8.tf32, double-buffered static SMEM.
// ---------------------------------------------------------------------------
#define ASZ (128 * 20)
#define BSZ (16 * 72)
__global__ void __launch_bounds__(256) gemm_tc(const float* __restrict__ bias,
                                               int K, int layer) {
    const uint32_t* A  = (const uint32_t*)(layer ? g_H0  : g_X0);
    const uint32_t* Bm = (const uint32_t*)(layer ? g_Wt1 : g_Wt0);
    float* C           = layer ? g_GI1 : g_GI0;
    __shared__ uint32_t sm[2][ASZ + BSZ];

    const int tid = threadIdx.x;
    const int lane = tid & 31, wid = tid >> 5;
    const int g = lane >> 2, tg = lane & 3;
    const int warp_m = (wid & 3) * 32;
    const int warp_n = (wid >> 2) * 32;
    const int m0 = blockIdx.y * 128, n0 = blockIdx.x * 64;

    float acc[2][4][4] = {};
    const int ntiles = (K + 15) / 16;
    const int br = tid >> 4, bc4 = tid & 15;

    uint4 la[2], lb;
#pragma unroll
    for (int i = 0; i < 2; i++) {
        int idx = tid + i * 256;
        int r = idx >> 2, c4 = idx & 3;
        int kk = c4 * 4;
        uint4 v = make_uint4(0u, 0u, 0u, 0u);
        if (kk + 3 < K) v = *(const uint4*)&A[(m0 + r) * K + kk];
        else {
            if (kk + 0 < K) v.x = A[(m0 + r) * K + kk + 0];
            if (kk + 1 < K) v.y = A[(m0 + r) * K + kk + 1];
            if (kk + 2 < K) v.z = A[(m0 + r) * K + kk + 2];
            if (kk + 3 < K) v.w = A[(m0 + r) * K + kk + 3];
        }
        la[i] = v;
    }
    {
        lb = make_uint4(0u, 0u, 0u, 0u);
        if (br < K) lb = *(const uint4*)&Bm[br * NT + n0 + bc4 * 4];
    }
#pragma unroll
    for (int i = 0; i < 2; i++) {
        int idx = tid + i * 256;
        int r = idx >> 2, c4 = idx & 3;
        *(uint4*)&sm[0][r * 20 + c4 * 4] = la[i];
    }
    *(uint4*)&sm[0][ASZ + br * 72 + bc4 * 4] = lb;
    __syncthreads();

    int cur = 0;
    for (int t = 0; t < ntiles; t++) {
        if (t + 1 < ntiles) {
            const int k0 = (t + 1) * 16;
#pragma unroll
            for (int i = 0; i < 2; i++) {
                int idx = tid + i * 256;
                int r = idx >> 2, c4 = idx & 3;
                int kk = k0 + c4 * 4;
                uint4 v = make_uint4(0u, 0u, 0u, 0u);
                if (kk + 3 < K) v = *(const uint4*)&A[(m0 + r) * K + kk];
                else {
                    if (kk + 0 < K) v.x = A[(m0 + r) * K + kk + 0];
                    if (kk + 1 < K) v.y = A[(m0 + r) * K + kk + 1];
                    if (kk + 2 < K) v.z = A[(m0 + r) * K + kk + 2];
                    if (kk + 3 < K) v.w = A[(m0 + r) * K + kk + 3];
                }
                la[i] = v;
            }
            int kk = k0 + br;
            lb = make_uint4(0u, 0u, 0u, 0u);
            if (kk < K) lb = *(const uint4*)&Bm[kk * NT + n0 + bc4 * 4];
        }
        const uint32_t* As = sm[cur];
        const uint32_t* Bs = sm[cur] + ASZ;
#pragma unroll
        for (int k8 = 0; k8 < 16; k8 += 8) {
            uint32_t a[2][4], b[4][2];
#pragma unroll
            for (int mi = 0; mi < 2; mi++) {
                int row = warp_m + mi * 16;
                a[mi][0] = As[(row + g) * 20 + k8 + tg];
                a[mi][1] = As[(row + g + 8) * 20 + k8 + tg];
                a[mi][2] = As[(row + g) * 20 + k8 + tg + 4];
                a[mi][3] = As[(row + g + 8) * 20 + k8 + tg + 4];
            }
#pragma unroll
            for (int ni = 0; ni < 4; ni++) {
                int col = warp_n + ni * 8 + g;
                b[ni][0] = Bs[(k8 + tg) * 72 + col];
                b[ni][1] = Bs[(k8 + tg + 4) * 72 + col];
            }
#pragma unroll
            for (int mi = 0; mi < 2; mi++)
#pragma unroll
                for (int ni = 0; ni < 4; ni++)
                    mma_tf32(acc[mi][ni], a[mi], b[ni]);
        }
        if (t + 1 < ntiles) {
            uint32_t* d = sm[cur ^ 1];
#pragma unroll
            for (int i = 0; i < 2; i++) {
                int idx = tid + i * 256;
                int r = idx >> 2, c4 = idx & 3;
                *(uint4*)&d[r * 20 + c4 * 4] = la[i];
            }
            *(uint4*)&d[ASZ + br * 72 + bc4 * 4] = lb;
        }
        __syncthreads();
        cur ^= 1;
    }

#pragma unroll
    for (int mi = 0; mi < 2; mi++) {
        int r0 = m0 + warp_m + mi * 16 + g;
        int r1 = r0 + 8;
#pragma unroll
        for (int ni = 0; ni < 4; ni++) {
            int c = n0 + warp_n + ni * 8 + tg * 2;
            float2 bv = *(const float2*)&bias[c];
            float2 o0, o1;
            o0.x = acc[mi][ni][0] + bv.x; o0.y = acc[mi][ni][1] + bv.y;
            o1.x = acc[mi][ni][2] + bv.x; o1.y = acc[mi][ni][3] + bv.y;
            *(float2*)&C[(size_t)r0 * NT + c] = o0;
            *(float2*)&C[(size_t)r1 * NT + c] = o1;
        }
    }
}

// ---------------------------------------------------------------------------
// Cluster-resident LSTM recurrence — R8 structure, fast gates (only delta).
// ---------------------------------------------------------------------------
__global__ void __cluster_dims__(4, 1, 1) __launch_bounds__(224, 1)
lstm_rec(const float* __restrict__ Whh, int layer) {
    const float* GI = layer ? g_GI1 : g_GI0;
    float* Hout     = layer ? g_H1  : g_H0;
    __shared__ __align__(16) float hbuf[2 * 2 * 200];  // [ping][batch01][j]
    __shared__ __align__(16) float ag[400];            // [gate][j][batch01]

    const int tid = threadIdx.x;     // 0..223
    uint32_t crank;
    asm("mov.u32 %0, %%cluster_ctarank;" : "=r"(crank));
    const int bg = blockIdx.y >> 1;
    const int d  = blockIdx.y & 1;
    const int bb0 = bg * 2;

    const int gate = (tid < 200) ? (tid / 50) : 0;
    const int jl   = (tid < 200) ? (tid % 50) : 0;
    const int jglob = (int)crank * 50 + jl;

    const float* WhhD = Whh + (size_t)d * (G * H);

    uint64_t upair[100];
    if (tid < 200) {
        const ulonglong2* Urow =
            (const ulonglong2*)(WhhD + (size_t)(gate * 200 + jglob) * 200);
#pragma unroll
        for (int kq = 0; kq < 50; kq++) {
            ulonglong2 t = Urow[kq];
            upair[2 * kq] = t.x;
            upair[2 * kq + 1] = t.y;
        }
    }
    for (int idx = tid; idx < 800; idx += 224) hbuf[idx] = 0.0f;
    __syncthreads();
    CLUSTER_SYNC_();   // peers' hbuf zeroed before any remote h store

    const uint32_t hb_u32 = smem_u32(hbuf);
    float cst = 0.0f;
    int p = 0;

    for (int step = 0; step < 128; step++) {
        const int tstep = d ? (127 - step) : step;
        // ---- phase A: gate pre-activations ----
        if (tid < 200) {
            const float* gb = GI + (size_t)(tstep * B + bb0) * NT + d * 800
                              + gate * 200 + jglob;
            float gi0 = gb[0];
            float gi1 = gb[NT];
            const ulonglong2* hp0 = (const ulonglong2*)(hbuf + (p * 2 + 0) * 200);
            const ulonglong2* hp1 = (const ulonglong2*)(hbuf + (p * 2 + 1) * 200);
            uint64_t a00 = 0, a01 = 0, a10 = 0, a11 = 0;
#pragma unroll
            for (int kq = 0; kq < 50; kq++) {
                ulonglong2 h0 = hp0[kq];
                ulonglong2 h1 = hp1[kq];
                a00 = fma2(upair[2 * kq],     h0.x, a00);
                a01 = fma2(upair[2 * kq + 1], h0.y, a01);
                a10 = fma2(upair[2 * kq],     h1.x, a10);
                a11 = fma2(upair[2 * kq + 1], h1.y, a11);
            }
            float2 s00 = unpack2(a00), s01 = unpack2(a01);
            float2 s10 = unpack2(a10), s11 = unpack2(a11);
            ag[gate * 100 + jl * 2 + 0] = (s00.x + s00.y) + (s01.x + s01.y) + gi0;
            ag[gate * 100 + jl * 2 + 1] = (s10.x + s10.y) + (s11.x + s11.y) + gi1;
        }
        __syncthreads();
        // ---- phase B: cell update + cluster h broadcast (fast gates) ----
        if (tid < 100) {
            float aI = ag[tid], aF = ag[100 + tid], aG = ag[200 + tid], aO = ag[300 + tid];
            cst = fsig(aF) * cst + fsig(aI) * ftanh(aG);
            float hv = fsig(aO) * ftanh(cst);
            const int b = tid & 1, jlc = tid >> 1;
            const int jg = (int)crank * 50 + jlc;
            const int pn = p ^ 1;
            const uint32_t ha = hb_u32 + (uint32_t)((((pn * 2 + b) * 200) + jg) * 4);
            st_cluster_f32(ha, 0, hv);
            st_cluster_f32(ha, 1, hv);
            st_cluster_f32(ha, 2, hv);
            st_cluster_f32(ha, 3, hv);
            float hstore = layer ? hv : __uint_as_float(f2tf32(hv));
            Hout[(size_t)(tstep * B + bb0 + b) * 400 + d * 200 + jg] = hstore;
        }
        CLUSTER_SYNC_();  // h published cluster-wide; also fences ag reuse
        p ^= 1;
    }
}

// ---------------------------------------------------------------------------
// Output projection
// ---------------------------------------------------------------------------
__global__ void out_proj(const float* __restrict__ ow,
                         const float* __restrict__ ob, float* __restrict__ out) {
    __shared__ float x[400];
    const int m = blockIdx.x; // s*B + b
    const int tid = threadIdx.x;
    for (int i = tid; i < 400; i += blockDim.x) x[i] = g_H1[m * 400 + i];
    __syncthreads();
    if (tid < 136) {
        const int tt = tid >> 3, l = tid & 7;
        float acc = 0.0f;
        for (int k = l; k < 400; k += 8) acc = fmaf(x[k], ow[tt * 400 + k], acc);
        unsigned mask = (tid < 128) ? 0xffffffffu : 0xffu;
        acc += __shfl_down_sync(mask, acc, 4, 8);
        acc += __shfl_down_sync(mask, acc, 2, 8);
        acc += __shfl_down_sync(mask, acc, 1, 8);
        if (l == 0) {
            int s = m >> 5, b = m & 31;
            out[(b * S + s) * T + tt] = sigf(acc + ob[tt]);
        }
    }
}

// ---------------------------------------------------------------------------
extern "C" void kernel_launch(void* const* d_in, const int* in_sizes, int n_in,
                              void* d_out, int out_size) {
    const int* words = (const int*)d_in[0];
    const float* emb = (const float*)d_in[3];
    const float* Wih0 = (const float*)d_in[7];
    const float* Whh0 = (const float*)d_in[8];
    const float* b0 = (const float*)d_in[9];
    const float* Wih1 = (const float*)d_in[10];
    const float* Whh1 = (const float*)d_in[11];
    const float* b1 = (const float*)d_in[12];
    const float* ow = (const float*)d_in[13];
    const float* ob = (const float*)d_in[14];
    float* out = (float*)d_out;

    prep<<<dim3(2500, 3), 256>>>(Wih0, Wih1, words, emb);
    gemm_tc<<<dim3(NT / 64, MROWS / 128), 256>>>(b0, 300, 0);
    lstm_rec<<<dim3(4, 32), 224>>>(Whh0, 0);
    gemm_tc<<<dim3(NT / 64, MROWS / 128), 256>>>(b1, 400, 1);
    lstm_rec<<<dim3(4, 32), 224>>>(Whh1, 1);
    out_proj<<<MROWS, 160>>>(ow, ob, out);
}

// round 15
// speedup vs baseline: 1.1594x; 1.0106x over previous
#include <cuda_runtime.h>
#include <cuda_bf16.h>
#include <math.h>
#include <stdint.h>

// Problem constants
#define S 128
#define B 32
#define E 300
#define H 200
#define G 800      // 4*H
#define NT 1600    // 2 dirs * G
#define MROWS 4096 // S*B
#define T 17

// Scratch (device globals). Wt*/X0/H0 hold tf32-converted bit patterns
// (stored as float bit-casts); GI*/H1 are true fp32.
__device__ float g_Wt0[300 * NT];
__device__ float g_Wt1[400 * NT];
__device__ float g_X0[MROWS * E];
__device__ float g_GI0[MROWS * NT];
__device__ float g_GI1[MROWS * NT];
__device__ float g_H0[MROWS * 400];
__device__ float g_H1[MROWS * 400];

__device__ __forceinline__ float sigf(float x) { return 1.0f / (1.0f + expf(-x)); }

__device__ __forceinline__ uint32_t smem_u32(const void* p) {
    uint32_t a;
    asm("{ .reg .u64 t; cvta.to.shared.u64 t, %1; cvt.u32.u64 %0, t; }" : "=r"(a) : "l"(p));
    return a;
}
__device__ __forceinline__ void st_cluster_f32(uint32_t laddr, uint32_t rank, float v) {
    uint32_t ra;
    asm volatile("mapa.shared::cluster.u32 %0, %1, %2;" : "=r"(ra) : "r"(laddr), "r"(rank));
    asm volatile("st.shared::cluster.f32 [%0], %1;" :: "r"(ra), "f"(v) : "memory");
}
#define CL_ARRIVE() asm volatile("barrier.cluster.arrive.aligned;" ::: "memory")
#define CL_WAIT()   asm volatile("barrier.cluster.wait.aligned;" ::: "memory")
#define CLUSTER_SYNC_() do { CL_ARRIVE(); CL_WAIT(); } while (0)

__device__ __forceinline__ uint32_t f2tf32(float f) {
    uint32_t u;
    asm("cvt.rna.tf32.f32 %0, %1;" : "=r"(u) : "f"(f));
    return u;
}
__device__ __forceinline__ uint64_t fma2(uint64_t a, uint64_t b, uint64_t c) {
    uint64_t d;
    asm("fma.rn.f32x2 %0, %1, %2, %3;" : "=l"(d) : "l"(a), "l"(b), "l"(c));
    return d;
}
__device__ __forceinline__ float2 unpack2(uint64_t v) {
    uint32_t lo, hi;
    asm("mov.b64 {%0,%1}, %2;" : "=r"(lo), "=r"(hi) : "l"(v));
    return make_float2(__uint_as_float(lo), __uint_as_float(hi));
}
__device__ __forceinline__ void mma_tf32(float* c, const uint32_t* a, const uint32_t* b) {
    asm volatile(
        "mma.sync.aligned.m16n8k8.row.col.f32.tf32.tf32.f32 "
        "{%0,%1,%2,%3}, {%4,%5,%6,%7}, {%8,%9}, {%0,%1,%2,%3};"
        : "+f"(c[0]), "+f"(c[1]), "+f"(c[2]), "+f"(c[3])
        : "r"(a[0]), "r"(a[1]), "r"(a[2]), "r"(a[3]), "r"(b[0]), "r"(b[1]));
}

// ---------------------------------------------------------------------------
// Fused prep
// ---------------------------------------------------------------------------
__global__ void prep(const float* __restrict__ Wih0, const float* __restrict__ Wih1,
                     const int* __restrict__ words, const float* __restrict__ emb) {
    const int task = blockIdx.y;
    const int idx = blockIdx.x * 256 + threadIdx.x;
    if (task == 0) {
        if (idx < NT * 300) {
            int n = idx / 300, k = idx - n * 300;
            g_Wt0[k * NT + n] = __uint_as_float(f2tf32(Wih0[idx]));
        }
    } else if (task == 1) {
        if (idx < NT * 400) {
            int n = idx / 400, k = idx - n * 400;
            g_Wt1[k * NT + n] = __uint_as_float(f2tf32(Wih1[idx]));
        }
    } else {
        if (idx < MROWS * 75) {
            int m = idx / 75, c4 = idx - m * 75;
            int s = m >> 5, b = m & 31;
            int w = words[b * S + s];
            float4 v = ((const float4*)(emb + (long long)w * E))[c4];
            float4 o;
            o.x = __uint_as_float(f2tf32(v.x));
            o.y = __uint_as_float(f2tf32(v.y));
            o.z = __uint_as_float(f2tf32(v.z));
            o.w = __uint_as_float(f2tf32(v.w));
            ((float4*)g_X0)[idx] = o;
        }
    }
}

// ---------------------------------------------------------------------------
// tf32 tensor-core GEMM. BM=128, BN=64, BK=16, 256 threads, warp tile 32x32.
// CHANGE vs R8: ALL fragment loads for the BK=16 tile are issued as one
// batch (32 LDS in flight -> single latency exposure), then all 16 mma.
// ---------------------------------------------------------------------------
#define ASZ (128 * 20)
#define BSZ (16 * 72)
__global__ void __launch_bounds__(256) gemm_tc(const float* __restrict__ bias,
                                               int K, int layer) {
    const uint32_t* A  = (const uint32_t*)(layer ? g_H0  : g_X0);
    const uint32_t* Bm = (const uint32_t*)(layer ? g_Wt1 : g_Wt0);
    float* C           = layer ? g_GI1 : g_GI0;
    __shared__ uint32_t sm[2][ASZ + BSZ];

    const int tid = threadIdx.x;
    const int lane = tid & 31, wid = tid >> 5;
    const int g = lane >> 2, tg = lane & 3;
    const int warp_m = (wid & 3) * 32;
    const int warp_n = (wid >> 2) * 32;
    const int m0 = blockIdx.y * 128, n0 = blockIdx.x * 64;

    float acc[2][4][4] = {};
    const int ntiles = (K + 15) / 16;
    const int br = tid >> 4, bc4 = tid & 15;

    uint4 la[2], lb;
#pragma unroll
    for (int i = 0; i < 2; i++) {
        int idx = tid + i * 256;
        int r = idx >> 2, c4 = idx & 3;
        int kk = c4 * 4;
        uint4 v = make_uint4(0u, 0u, 0u, 0u);
        if (kk + 3 < K) v = *(const uint4*)&A[(m0 + r) * K + kk];
        else {
            if (kk + 0 < K) v.x = A[(m0 + r) * K + kk + 0];
            if (kk + 1 < K) v.y = A[(m0 + r) * K + kk + 1];
            if (kk + 2 < K) v.z = A[(m0 + r) * K + kk + 2];
            if (kk + 3 < K) v.w = A[(m0 + r) * K + kk + 3];
        }
        la[i] = v;
    }
    {
        lb = make_uint4(0u, 0u, 0u, 0u);
        if (br < K) lb = *(const uint4*)&Bm[br * NT + n0 + bc4 * 4];
    }
#pragma unroll
    for (int i = 0; i < 2; i++) {
        int idx = tid + i * 256;
        int r = idx >> 2, c4 = idx & 3;
        *(uint4*)&sm[0][r * 20 + c4 * 4] = la[i];
    }
    *(uint4*)&sm[0][ASZ + br * 72 + bc4 * 4] = lb;
    __syncthreads();

    int cur = 0;
    for (int t = 0; t < ntiles; t++) {
        if (t + 1 < ntiles) {
            const int k0 = (t + 1) * 16;
#pragma unroll
            for (int i = 0; i < 2; i++) {
                int idx = tid + i * 256;
                int r = idx >> 2, c4 = idx & 3;
                int kk = k0 + c4 * 4;
                uint4 v = make_uint4(0u, 0u, 0u, 0u);
                if (kk + 3 < K) v = *(const uint4*)&A[(m0 + r) * K + kk];
                else {
                    if (kk + 0 < K) v.x = A[(m0 + r) * K + kk + 0];
                    if (kk + 1 < K) v.y = A[(m0 + r) * K + kk + 1];
                    if (kk + 2 < K) v.z = A[(m0 + r) * K + kk + 2];
                    if (kk + 3 < K) v.w = A[(m0 + r) * K + kk + 3];
                }
                la[i] = v;
            }
            int kk = k0 + br;
            lb = make_uint4(0u, 0u, 0u, 0u);
            if (kk < K) lb = *(const uint4*)&Bm[kk * NT + n0 + bc4 * 4];
        }
        const uint32_t* As = sm[cur];
        const uint32_t* Bs = sm[cur] + ASZ;
        // --- batched fragment loads for the whole BK=16 tile ---
        uint32_t a[2][2][4], b[2][4][2];
#pragma unroll
        for (int h = 0; h < 2; h++) {
            const int k8 = h * 8;
#pragma unroll
            for (int mi = 0; mi < 2; mi++) {
                int row = warp_m + mi * 16;
                a[h][mi][0] = As[(row + g) * 20 + k8 + tg];
                a[h][mi][1] = As[(row + g + 8) * 20 + k8 + tg];
                a[h][mi][2] = As[(row + g) * 20 + k8 + tg + 4];
                a[h][mi][3] = As[(row + g + 8) * 20 + k8 + tg + 4];
            }
#pragma unroll
            for (int ni = 0; ni < 4; ni++) {
                int col = warp_n + ni * 8 + g;
                b[h][ni][0] = Bs[(k8 + tg) * 72 + col];
                b[h][ni][1] = Bs[(k8 + tg + 4) * 72 + col];
            }
        }
#pragma unroll
        for (int h = 0; h < 2; h++)
#pragma unroll
            for (int mi = 0; mi < 2; mi++)
#pragma unroll
                for (int ni = 0; ni < 4; ni++)
                    mma_tf32(acc[mi][ni], a[h][mi], b[h][ni]);
        if (t + 1 < ntiles) {
            uint32_t* d = sm[cur ^ 1];
#pragma unroll
            for (int i = 0; i < 2; i++) {
                int idx = tid + i * 256;
                int r = idx >> 2, c4 = idx & 3;
                *(uint4*)&d[r * 20 + c4 * 4] = la[i];
            }
            *(uint4*)&d[ASZ + br * 72 + bc4 * 4] = lb;
        }
        __syncthreads();
        cur ^= 1;
    }

#pragma unroll
    for (int mi = 0; mi < 2; mi++) {
        int r0 = m0 + warp_m + mi * 16 + g;
        int r1 = r0 + 8;
#pragma unroll
        for (int ni = 0; ni < 4; ni++) {
            int c = n0 + warp_n + ni * 8 + tg * 2;
            float2 bv = *(const float2*)&bias[c];
            float2 o0, o1;
            o0.x = acc[mi][ni][0] + bv.x; o0.y = acc[mi][ni][1] + bv.y;
            o1.x = acc[mi][ni][2] + bv.x; o1.y = acc[mi][ni][3] + bv.y;
            *(float2*)&C[(size_t)r0 * NT + c] = o0;
            *(float2*)&C[(size_t)r1 * NT + c] = o1;
        }
    }
}

// ---------------------------------------------------------------------------
// Cluster-resident LSTM recurrence — R8 VERBATIM (best measured).
// ---------------------------------------------------------------------------
__global__ void __cluster_dims__(4, 1, 1) __launch_bounds__(224, 1)
lstm_rec(const float* __restrict__ Whh, int layer) {
    const float* GI = layer ? g_GI1 : g_GI0;
    float* Hout     = layer ? g_H1  : g_H0;
    __shared__ __align__(16) float hbuf[2 * 2 * 200];  // [ping][batch01][j]
    __shared__ __align__(16) float ag[400];            // [gate][j][batch01]

    const int tid = threadIdx.x;     // 0..223
    uint32_t crank;
    asm("mov.u32 %0, %%cluster_ctarank;" : "=r"(crank));
    const int bg = blockIdx.y >> 1;
    const int d  = blockIdx.y & 1;
    const int bb0 = bg * 2;

    const int gate = (tid < 200) ? (tid / 50) : 0;
    const int jl   = (tid < 200) ? (tid % 50) : 0;
    const int jglob = (int)crank * 50 + jl;

    const float* WhhD = Whh + (size_t)d * (G * H);

    uint64_t upair[100];
    if (tid < 200) {
        const ulonglong2* Urow =
            (const ulonglong2*)(WhhD + (size_t)(gate * 200 + jglob) * 200);
#pragma unroll
        for (int kq = 0; kq < 50; kq++) {
            ulonglong2 t = Urow[kq];
            upair[2 * kq] = t.x;
            upair[2 * kq + 1] = t.y;
        }
    }
    for (int idx = tid; idx < 800; idx += 224) hbuf[idx] = 0.0f;
    __syncthreads();
    CLUSTER_SYNC_();   // peers' hbuf zeroed before any remote h store

    const uint32_t hb_u32 = smem_u32(hbuf);
    float cst = 0.0f;
    int p = 0;

    for (int step = 0; step < 128; step++) {
        const int tstep = d ? (127 - step) : step;
        // ---- phase A: gate pre-activations ----
        if (tid < 200) {
            const float* gb = GI + (size_t)(tstep * B + bb0) * NT + d * 800
                              + gate * 200 + jglob;
            float gi0 = gb[0];
            float gi1 = gb[NT];
            const ulonglong2* hp0 = (const ulonglong2*)(hbuf + (p * 2 + 0) * 200);
            const ulonglong2* hp1 = (const ulonglong2*)(hbuf + (p * 2 + 1) * 200);
            uint64_t a00 = 0, a01 = 0, a10 = 0, a11 = 0;
#pragma unroll
            for (int kq = 0; kq < 50; kq++) {
                ulonglong2 h0 = hp0[kq];
                ulonglong2 h1 = hp1[kq];
                a00 = fma2(upair[2 * kq],     h0.x, a00);
                a01 = fma2(upair[2 * kq + 1], h0.y, a01);
                a10 = fma2(upair[2 * kq],     h1.x, a10);
                a11 = fma2(upair[2 * kq + 1], h1.y, a11);
            }
            float2 s00 = unpack2(a00), s01 = unpack2(a01);
            float2 s10 = unpack2(a10), s11 = unpack2(a11);
            ag[gate * 100 + jl * 2 + 0] = (s00.x + s00.y) + (s01.x + s01.y) + gi0;
            ag[gate * 100 + jl * 2 + 1] = (s10.x + s10.y) + (s11.x + s11.y) + gi1;
        }
        __syncthreads();
        // ---- phase B: cell update + cluster h broadcast ----
        if (tid < 100) {
            float aI = ag[tid], aF = ag[100 + tid], aG = ag[200 + tid], aO = ag[300 + tid];
            cst = sigf(aF) * cst + sigf(aI) * tanhf(aG);
            float hv = sigf(aO) * tanhf(cst);
            const int b = tid & 1, jlc = tid >> 1;
            const int jg = (int)crank * 50 + jlc;
            const int pn = p ^ 1;
            const uint32_t ha = hb_u32 + (uint32_t)((((pn * 2 + b) * 200) + jg) * 4);
            st_cluster_f32(ha, 0, hv);
            st_cluster_f32(ha, 1, hv);
            st_cluster_f32(ha, 2, hv);
            st_cluster_f32(ha, 3, hv);
            float hstore = layer ? hv : __uint_as_float(f2tf32(hv));
            Hout[(size_t)(tstep * B + bb0 + b) * 400 + d * 200 + jg] = hstore;
        }
        CLUSTER_SYNC_();  // h published cluster-wide; also fences ag reuse
        p ^= 1;
    }
}

// ---------------------------------------------------------------------------
// Output projection
// ---------------------------------------------------------------------------
__global__ void out_proj(const float* __restrict__ ow,
                         const float* __restrict__ ob, float* __restrict__ out) {
    __shared__ float x[400];
    const int m = blockIdx.x; // s*B + b
    const int tid = threadIdx.x;
    for (int i = tid; i < 400; i += blockDim.x) x[i] = g_H1[m * 400 + i];
    __syncthreads();
    if (tid < 136) {
        const int tt = tid >> 3, l = tid & 7;
        float acc = 0.0f;
        for (int k = l; k < 400; k += 8) acc = fmaf(x[k], ow[tt * 400 + k], acc);
        unsigned mask = (tid < 128) ? 0xffffffffu : 0xffu;
        acc += __shfl_down_sync(mask, acc, 4, 8);
        acc += __shfl_down_sync(mask, acc, 2, 8);
        acc += __shfl_down_sync(mask, acc, 1, 8);
        if (l == 0) {
            int s = m >> 5, b = m & 31;
            out[(b * S + s) * T + tt] = sigf(acc + ob[tt]);
        }
    }
}

// ---------------------------------------------------------------------------
extern "C" void kernel_launch(void* const* d_in, const int* in_sizes, int n_in,
                              void* d_out, int out_size) {
    const int* words = (const int*)d_in[0];
    const float* emb = (const float*)d_in[3];
    const float* Wih0 = (const float*)d_in[7];
    const float* Whh0 = (const float*)d_in[8];
    const float* b0 = (const float*)d_in[9];
    const float* Wih1 = (const float*)d_in[10];
    const float* Whh1 = (const float*)d_in[11];
    const float* b1 = (const float*)d_in[12];
    const float* ow = (const float*)d_in[13];
    const float* ob = (const float*)d_in[14];
    float* out = (float*)d_out;

    prep<<<dim3(2500, 3), 256>>>(Wih0, Wih1, words, emb);
    gemm_tc<<<dim3(NT / 64, MROWS / 128), 256>>>(b0, 300, 0);
    lstm_rec<<<dim3(4, 32), 224>>>(Whh0, 0);
    gemm_tc<<<dim3(NT / 64, MROWS / 128), 256>>>(b1, 400, 1);
    lstm_rec<<<dim3(4, 32), 224>>>(Whh1, 1);
    out_proj<<<MROWS, 160>>>(ow, ob, out);
}

// round 16
// speedup vs baseline: 1.2066x; 1.0407x over previous
#include <cuda_runtime.h>
#include <cuda_bf16.h>
#include <math.h>
#include <stdint.h>

// Problem constants
#define S 128
#define B 32
#define E 300
#define H 200
#define G 800      // 4*H
#define NT 1600    // 2 dirs * G
#define MROWS 4096 // S*B
#define T 17

// Scratch (device globals). Wt*/X0/H0 hold tf32-converted bit patterns
// (stored as float bit-casts); GI*/H1 are true fp32.
__device__ float g_Wt0[300 * NT];
__device__ float g_Wt1[400 * NT];
__device__ float g_X0[MROWS * E];
__device__ float g_GI0[MROWS * NT];
__device__ float g_GI1[MROWS * NT];
__device__ float g_H0[MROWS * 400];
__device__ float g_H1[MROWS * 400];

__device__ __forceinline__ float sigf(float x) { return 1.0f / (1.0f + expf(-x)); }

__device__ __forceinline__ uint32_t smem_u32(const void* p) {
    uint32_t a;
    asm("{ .reg .u64 t; cvta.to.shared.u64 t, %1; cvt.u32.u64 %0, t; }" : "=r"(a) : "l"(p));
    return a;
}
__device__ __forceinline__ void st_cluster_f32(uint32_t laddr, uint32_t rank, float v) {
    uint32_t ra;
    asm volatile("mapa.shared::cluster.u32 %0, %1, %2;" : "=r"(ra) : "r"(laddr), "r"(rank));
    asm volatile("st.shared::cluster.f32 [%0], %1;" :: "r"(ra), "f"(v) : "memory");
}
#define CL_ARRIVE() asm volatile("barrier.cluster.arrive.aligned;" ::: "memory")
#define CL_WAIT()   asm volatile("barrier.cluster.wait.aligned;" ::: "memory")
#define CLUSTER_SYNC_() do { CL_ARRIVE(); CL_WAIT(); } while (0)

__device__ __forceinline__ uint32_t f2tf32(float f) {
    uint32_t u;
    asm("cvt.rna.tf32.f32 %0, %1;" : "=r"(u) : "f"(f));
    return u;
}
__device__ __forceinline__ uint64_t fma2(uint64_t a, uint64_t b, uint64_t c) {
    uint64_t d;
    asm("fma.rn.f32x2 %0, %1, %2, %3;" : "=l"(d) : "l"(a), "l"(b), "l"(c));
    return d;
}
__device__ __forceinline__ float2 unpack2(uint64_t v) {
    uint32_t lo, hi;
    asm("mov.b64 {%0,%1}, %2;" : "=r"(lo), "=r"(hi) : "l"(v));
    return make_float2(__uint_as_float(lo), __uint_as_float(hi));
}
__device__ __forceinline__ void mma_tf32(float* c, const uint32_t* a, const uint32_t* b) {
    asm volatile(
        "mma.sync.aligned.m16n8k8.row.col.f32.tf32.tf32.f32 "
        "{%0,%1,%2,%3}, {%4,%5,%6,%7}, {%8,%9}, {%0,%1,%2,%3};"
        : "+f"(c[0]), "+f"(c[1]), "+f"(c[2]), "+f"(c[3])
        : "r"(a[0]), "r"(a[1]), "r"(a[2]), "r"(a[3]), "r"(b[0]), "r"(b[1]));
}
__device__ __forceinline__ void cpasync16(uint32_t dst, const void* src, int src_bytes) {
    asm volatile("cp.async.cg.shared.global [%0], [%1], 16, %2;"
                 :: "r"(dst), "l"(src), "r"(src_bytes) : "memory");
}
#define CP_COMMIT() asm volatile("cp.async.commit_group;" ::: "memory")
#define CP_WAIT2()  asm volatile("cp.async.wait_group 2;" ::: "memory")

// ---------------------------------------------------------------------------
// Fused prep
// ---------------------------------------------------------------------------
__global__ void prep(const float* __restrict__ Wih0, const float* __restrict__ Wih1,
                     const int* __restrict__ words, const float* __restrict__ emb) {
    const int task = blockIdx.y;
    const int idx = blockIdx.x * 256 + threadIdx.x;
    if (task == 0) {
        if (idx < NT * 300) {
            int n = idx / 300, k = idx - n * 300;
            g_Wt0[k * NT + n] = __uint_as_float(f2tf32(Wih0[idx]));
        }
    } else if (task == 1) {
        if (idx < NT * 400) {
            int n = idx / 400, k = idx - n * 400;
            g_Wt1[k * NT + n] = __uint_as_float(f2tf32(Wih1[idx]));
        }
    } else {
        if (idx < MROWS * 75) {
            int m = idx / 75, c4 = idx - m * 75;
            int s = m >> 5, b = m & 31;
            int w = words[b * S + s];
            float4 v = ((const float4*)(emb + (long long)w * E))[c4];
            float4 o;
            o.x = __uint_as_float(f2tf32(v.x));
            o.y = __uint_as_float(f2tf32(v.y));
            o.z = __uint_as_float(f2tf32(v.z));
            o.w = __uint_as_float(f2tf32(v.w));
            ((float4*)g_X0)[idx] = o;
        }
    }
}

// ---------------------------------------------------------------------------
// tf32 tensor-core GEMM with 4-stage cp.async pipeline.
// BM=128, BN=64, BK=16, 256 threads (8 warps, 4x2), warp tile 32x32.
// As: [128][20] pad; Bs: [16][72] pad (layouts identical to R8 -> same frag
// addressing). Global->SMEM via cp.async.cg 16B (no register staging).
// One commit_group per iteration (empty at tail) keeps wait_group 2 exact.
// ---------------------------------------------------------------------------
#define ASZ (128 * 20)
#define BSZ (16 * 72)
#define STG (ASZ + BSZ)
#define NSTAGE 4
#define GEMM_SMEM (NSTAGE * STG * 4)
__global__ void __launch_bounds__(256) gemm_tc(const float* __restrict__ bias,
                                               int K, int layer) {
    const uint32_t* A  = (const uint32_t*)(layer ? g_H0  : g_X0);
    const uint32_t* Bm = (const uint32_t*)(layer ? g_Wt1 : g_Wt0);
    float* C           = layer ? g_GI1 : g_GI0;
    extern __shared__ uint32_t smd[];
    const uint32_t smbase = smem_u32(smd);

    const int tid = threadIdx.x;
    const int lane = tid & 31, wid = tid >> 5;
    const int g = lane >> 2, tg = lane & 3;
    const int warp_m = (wid & 3) * 32;
    const int warp_n = (wid >> 2) * 32;
    const int m0 = blockIdx.y * 128, n0 = blockIdx.x * 64;

    float acc[2][4][4] = {};
    const int ntiles = (K + 15) / 16;
    // cp.async indices: A = 2 chunks/thread, B = 1 chunk/thread
    const int ar0 = tid >> 2, ac0 = tid & 3;           // chunk 0: rows 0..63
    const int ar1 = (tid + 256) >> 2, ac1 = tid & 3;   // chunk 1: rows 64..127
    const int br = tid >> 4, bc4 = tid & 15;

    // issue stage s for k-offset k0
    auto issue = [&](int s, int k0) {
        const uint32_t st = smbase + (uint32_t)(s * STG * 4);
        // A chunk 0
        {
            int kk = k0 + ac0 * 4;
            int v = K - kk; v = v < 0 ? 0 : (v > 4 ? 4 : v);
            const uint32_t* src = &A[(size_t)(m0 + ar0) * K + (v ? kk : 0)];
            cpasync16(st + (uint32_t)((ar0 * 20 + ac0 * 4) * 4), src, v * 4);
        }
        // A chunk 1
        {
            int kk = k0 + ac1 * 4;
            int v = K - kk; v = v < 0 ? 0 : (v > 4 ? 4 : v);
            const uint32_t* src = &A[(size_t)(m0 + ar1) * K + (v ? kk : 0)];
            cpasync16(st + (uint32_t)((ar1 * 20 + ac1 * 4) * 4), src, v * 4);
        }
        // B chunk
        {
            int kk = k0 + br;
            int v = (kk < K) ? 16 : 0;
            const uint32_t* src = &Bm[(size_t)(v ? kk : 0) * NT + n0 + bc4 * 4];
            cpasync16(st + (uint32_t)((ASZ + br * 72 + bc4 * 4) * 4), src, v);
        }
    };

    // prologue: stages 0..2
#pragma unroll
    for (int s = 0; s < NSTAGE - 1; s++) {
        if (s < ntiles) issue(s, s * 16);
        CP_COMMIT();
    }

    for (int t = 0; t < ntiles; t++) {
        CP_WAIT2();
        __syncthreads();
        const uint32_t* As = smd + (t & 3) * STG;
        const uint32_t* Bs = As + ASZ;
#pragma unroll
        for (int k8 = 0; k8 < 16; k8 += 8) {
            uint32_t a[2][4], b[4][2];
#pragma unroll
            for (int mi = 0; mi < 2; mi++) {
                int row = warp_m + mi * 16;
                a[mi][0] = As[(row + g) * 20 + k8 + tg];
                a[mi][1] = As[(row + g + 8) * 20 + k8 + tg];
                a[mi][2] = As[(row + g) * 20 + k8 + tg + 4];
                a[mi][3] = As[(row + g + 8) * 20 + k8 + tg + 4];
            }
#pragma unroll
            for (int ni = 0; ni < 4; ni++) {
                int col = warp_n + ni * 8 + g;
                b[ni][0] = Bs[(k8 + tg) * 72 + col];
                b[ni][1] = Bs[(k8 + tg + 4) * 72 + col];
            }
#pragma unroll
            for (int mi = 0; mi < 2; mi++)
#pragma unroll
                for (int ni = 0; ni < 4; ni++)
                    mma_tf32(acc[mi][ni], a[mi], b[ni]);
        }
        const int tn = t + NSTAGE - 1;
        if (tn < ntiles) issue(tn & 3, tn * 16);
        CP_COMMIT();   // empty group at tail keeps the wait count uniform
    }

#pragma unroll
    for (int mi = 0; mi < 2; mi++) {
        int r0 = m0 + warp_m + mi * 16 + g;
        int r1 = r0 + 8;
#pragma unroll
        for (int ni = 0; ni < 4; ni++) {
            int c = n0 + warp_n + ni * 8 + tg * 2;
            float2 bv = *(const float2*)&bias[c];
            float2 o0, o1;
            o0.x = acc[mi][ni][0] + bv.x; o0.y = acc[mi][ni][1] + bv.y;
            o1.x = acc[mi][ni][2] + bv.x; o1.y = acc[mi][ni][3] + bv.y;
            *(float2*)&C[(size_t)r0 * NT + c] = o0;
            *(float2*)&C[(size_t)r1 * NT + c] = o1;
        }
    }
}

// ---------------------------------------------------------------------------
// Cluster-resident LSTM recurrence — R8 VERBATIM (best measured).
// ---------------------------------------------------------------------------
__global__ void __cluster_dims__(4, 1, 1) __launch_bounds__(224, 1)
lstm_rec(const float* __restrict__ Whh, int layer) {
    const float* GI = layer ? g_GI1 : g_GI0;
    float* Hout     = layer ? g_H1  : g_H0;
    __shared__ __align__(16) float hbuf[2 * 2 * 200];  // [ping][batch01][j]
    __shared__ __align__(16) float ag[400];            // [gate][j][batch01]

    const int tid = threadIdx.x;     // 0..223
    uint32_t crank;
    asm("mov.u32 %0, %%cluster_ctarank;" : "=r"(crank));
    const int bg = blockIdx.y >> 1;
    const int d  = blockIdx.y & 1;
    const int bb0 = bg * 2;

    const int gate = (tid < 200) ? (tid / 50) : 0;
    const int jl   = (tid < 200) ? (tid % 50) : 0;
    const int jglob = (int)crank * 50 + jl;

    const float* WhhD = Whh + (size_t)d * (G * H);

    uint64_t upair[100];
    if (tid < 200) {
        const ulonglong2* Urow =
            (const ulonglong2*)(WhhD + (size_t)(gate * 200 + jglob) * 200);
#pragma unroll
        for (int kq = 0; kq < 50; kq++) {
            ulonglong2 t = Urow[kq];
            upair[2 * kq] = t.x;
            upair[2 * kq + 1] = t.y;
        }
    }
    for (int idx = tid; idx < 800; idx += 224) hbuf[idx] = 0.0f;
    __syncthreads();
    CLUSTER_SYNC_();   // peers' hbuf zeroed before any remote h store

    const uint32_t hb_u32 = smem_u32(hbuf);
    float cst = 0.0f;
    int p = 0;

    for (int step = 0; step < 128; step++) {
        const int tstep = d ? (127 - step) : step;
        // ---- phase A: gate pre-activations ----
        if (tid < 200) {
            const float* gb = GI + (size_t)(tstep * B + bb0) * NT + d * 800
                              + gate * 200 + jglob;
            float gi0 = gb[0];
            float gi1 = gb[NT];
            const ulonglong2* hp0 = (const ulonglong2*)(hbuf + (p * 2 + 0) * 200);
            const ulonglong2* hp1 = (const ulonglong2*)(hbuf + (p * 2 + 1) * 200);
            uint64_t a00 = 0, a01 = 0, a10 = 0, a11 = 0;
#pragma unroll
            for (int kq = 0; kq < 50; kq++) {
                ulonglong2 h0 = hp0[kq];
                ulonglong2 h1 = hp1[kq];
                a00 = fma2(upair[2 * kq],     h0.x, a00);
                a01 = fma2(upair[2 * kq + 1], h0.y, a01);
                a10 = fma2(upair[2 * kq],     h1.x, a10);
                a11 = fma2(upair[2 * kq + 1], h1.y, a11);
            }
            float2 s00 = unpack2(a00), s01 = unpack2(a01);
            float2 s10 = unpack2(a10), s11 = unpack2(a11);
            ag[gate * 100 + jl * 2 + 0] = (s00.x + s00.y) + (s01.x + s01.y) + gi0;
            ag[gate * 100 + jl * 2 + 1] = (s10.x + s10.y) + (s11.x + s11.y) + gi1;
        }
        __syncthreads();
        // ---- phase B: cell update + cluster h broadcast ----
        if (tid < 100) {
            float aI = ag[tid], aF = ag[100 + tid], aG = ag[200 + tid], aO = ag[300 + tid];
            cst = sigf(aF) * cst + sigf(aI) * tanhf(aG);
            float hv = sigf(aO) * tanhf(cst);
            const int b = tid & 1, jlc = tid >> 1;
            const int jg = (int)crank * 50 + jlc;
            const int pn = p ^ 1;
            const uint32_t ha = hb_u32 + (uint32_t)((((pn * 2 + b) * 200) + jg) * 4);
            st_cluster_f32(ha, 0, hv);
            st_cluster_f32(ha, 1, hv);
            st_cluster_f32(ha, 2, hv);
            st_cluster_f32(ha, 3, hv);
            float hstore = layer ? hv : __uint_as_float(f2tf32(hv));
            Hout[(size_t)(tstep * B + bb0 + b) * 400 + d * 200 + jg] = hstore;
        }
        CLUSTER_SYNC_();  // h published cluster-wide; also fences ag reuse
        p ^= 1;
    }
}

// ---------------------------------------------------------------------------
// Output projection
// ---------------------------------------------------------------------------
__global__ void out_proj(const float* __restrict__ ow,
                         const float* __restrict__ ob, float* __restrict__ out) {
    __shared__ float x[400];
    const int m = blockIdx.x; // s*B + b
    const int tid = threadIdx.x;
    for (int i = tid; i < 400; i += blockDim.x) x[i] = g_H1[m * 400 + i];
    __syncthreads();
    if (tid < 136) {
        const int tt = tid >> 3, l = tid & 7;
        float acc = 0.0f;
        for (int k = l; k < 400; k += 8) acc = fmaf(x[k], ow[tt * 400 + k], acc);
        unsigned mask = (tid < 128) ? 0xffffffffu : 0xffu;
        acc += __shfl_down_sync(mask, acc, 4, 8);
        acc += __shfl_down_sync(mask, acc, 2, 8);
        acc += __shfl_down_sync(mask, acc, 1, 8);
        if (l == 0) {
            int s = m >> 5, b = m & 31;
            out[(b * S + s) * T + tt] = sigf(acc + ob[tt]);
        }
    }
}

// ---------------------------------------------------------------------------
extern "C" void kernel_launch(void* const* d_in, const int* in_sizes, int n_in,
                              void* d_out, int out_size) {
    const int* words = (const int*)d_in[0];
    const float* emb = (const float*)d_in[3];
    const float* Wih0 = (const float*)d_in[7];
    const float* Whh0 = (const float*)d_in[8];
    const float* b0 = (const float*)d_in[9];
    const float* Wih1 = (const float*)d_in[10];
    const float* Whh1 = (const float*)d_in[11];
    const float* b1 = (const float*)d_in[12];
    const float* ow = (const float*)d_in[13];
    const float* ob = (const float*)d_in[14];
    float* out = (float*)d_out;

    // unconditional, capture-safe host call (proven pattern)
    cudaFuncSetAttribute(gemm_tc, cudaFuncAttributeMaxDynamicSharedMemorySize,
                         GEMM_SMEM);

    prep<<<dim3(2500, 3), 256>>>(Wih0, Wih1, words, emb);
    gemm_tc<<<dim3(NT / 64, MROWS / 128), 256, GEMM_SMEM>>>(b0, 300, 0);
    lstm_rec<<<dim3(4, 32), 224>>>(Whh0, 0);
    gemm_tc<<<dim3(NT / 64, MROWS / 128), 256, GEMM_SMEM>>>(b1, 400, 1);
    lstm_rec<<<dim3(4, 32), 224>>>(Whh1, 1);
    out_proj<<<MROWS, 160>>>(ow, ob, out);
}